// round 6
// baseline (speedup 1.0000x reference)
#include <cuda_runtime.h>
#include <cuda_bf16.h>
#include <stdint.h>

#define NNODES 100000
#define KNN 6
#define NEDGES 600000

// ---------------- device scratch (no allocation allowed) ----------------
__device__ float g_y [(size_t)NNODES * 128];   // node-level partial (x@Wa_top + ba)
__device__ float g_h1[(size_t)NNODES * 32];
__device__ float g_h2[(size_t)NNODES * 64];

// ---------------- PTX helpers (sm_80+: mma.sync / ldmatrix) ----------------
__device__ __forceinline__ uint32_t s2u(const void* p) {
    uint32_t a;
    asm("{ .reg .u64 t; cvta.to.shared.u64 t, %1; cvt.u32.u64 %0, t; }" : "=r"(a) : "l"(p));
    return a;
}
__device__ __forceinline__ void ldm_x4(uint32_t* r, uint32_t addr) {
    asm volatile("ldmatrix.sync.aligned.m8n8.x4.shared.b16 {%0,%1,%2,%3}, [%4];"
                 : "=r"(r[0]), "=r"(r[1]), "=r"(r[2]), "=r"(r[3]) : "r"(addr));
}
__device__ __forceinline__ void mma_bf16(float* c, const uint32_t* a, const uint32_t* b) {
    asm volatile("mma.sync.aligned.m16n8k16.row.col.f32.bf16.bf16.f32 "
                 "{%0,%1,%2,%3}, {%4,%5,%6,%7}, {%8,%9}, {%0,%1,%2,%3};"
                 : "+f"(c[0]), "+f"(c[1]), "+f"(c[2]), "+f"(c[3])
                 : "r"(a[0]), "r"(a[1]), "r"(a[2]), "r"(a[3]), "r"(b[0]), "r"(b[1]));
}
__device__ __forceinline__ uint32_t pack_bf2(__nv_bfloat16 a, __nv_bfloat16 b) {
    __nv_bfloat162 v = __halves2bfloat162(a, b);
    return *(uint32_t*)&v;
}

// ============ kernelN: y[node] = x @ Wa_top + ba  (warp per node) ============
template<int CIN, int H>
__global__ __launch_bounds__(256) void kernelN(const float* __restrict__ x,
                                               const float* __restrict__ Wa,
                                               const float* __restrict__ ba,
                                               float* __restrict__ y)
{
    constexpr int CPL = H / 32;
    __shared__ float sW[CIN * H];
    __shared__ float sb[H];
    for (int t = threadIdx.x; t < CIN * H; t += 256) sW[t] = Wa[t];
    for (int t = threadIdx.x; t < H;       t += 256) sb[t] = ba[t];
    __syncthreads();

    const int lane = threadIdx.x & 31;
    const int gw = (blockIdx.x * 256 + threadIdx.x) >> 5;
    const int nw = (gridDim.x * 256) >> 5;
    const int c0 = lane * CPL;

    for (int node = gw; node < NNODES; node += nw) {
        float acc[CPL];
        #pragma unroll
        for (int q = 0; q < CPL; q++) acc[q] = sb[c0 + q];
        #pragma unroll 4
        for (int c = 0; c < CIN; c++) {
            float xv = __ldg(&x[(size_t)node * CIN + c]);
            #pragma unroll
            for (int q = 0; q < CPL; q++) acc[q] = fmaf(xv, sW[c * H + c0 + q], acc[q]);
        }
        #pragma unroll
        for (int q = 0; q < CPL; q++) y[(size_t)node * H + c0 + q] = acc[q];
    }
}

// ============ fused stage2F: build A tile in smem from y/pos/src, MMA, 6-row max ===========
// M = 16 * (TH/32) rows; EP = floor(M/6)*6 real edges per tile. Warp w owns rows
// [16w,16w+16). NSPLIT: grid is split into NSPLIT groups; group g computes output
// columns [g*NC, (g+1)*NC) — B tile built once per CTA. z aliases the A region.
// C = Ah*Bh + Ah*Bl + Al*Bh with fp32 accumulators (split-bf16, 3 terms).
template<int H, int NC, int TH, int NSPLIT>
__global__ __launch_bounds__(TH, 2) void stage2F(const float* __restrict__ y,
                                                 const float* __restrict__ pos,
                                                 const int*   __restrict__ src,
                                                 const float* __restrict__ Wa,   // [(cin+3)][H]
                                                 int cin,
                                                 const float* __restrict__ Wb,   // [H][NOUT]
                                                 const float* __restrict__ bb,
                                                 int nout,
                                                 float* __restrict__ out)
{
    constexpr int M     = 16 * (TH / 32);
    constexpr int EP    = (M / KNN) * KNN;   // real edges per tile
    constexpr int NODES = M / KNN;
    constexpr int SA    = H + 8;             // padded A/B row stride (bf16 elems)
    constexpr int NP    = NC + 4;            // padded z row (floats)
    constexpr int NT8   = NC / 8;
    constexpr int OFF_AH = 0;
    constexpr int OFF_AL = M * SA * 2;
    constexpr int OFF_BH = 2 * M * SA * 2;
    constexpr int OFF_BL = OFF_BH + NC * SA * 2;
    constexpr int OFF_WP = OFF_BL + NC * SA * 2;       // 3*H floats
    constexpr int OFF_BB = OFF_WP + 3 * H * 4;         // NC floats
    constexpr int OFF_SJ = OFF_BB + NC * 4;            // M ints
    constexpr int OFF_SD = OFF_SJ + M * 4;             // EP*3 floats

    extern __shared__ char smem[];
    const uint32_t sb = s2u(smem);
    float* z   = (float*)smem;                    // aliases A region (NP <= SA)
    float* sWp = (float*)(smem + OFF_WP);
    float* sbb = (float*)(smem + OFF_BB);
    int*   sj  = (int*)  (smem + OFF_SJ);
    float* sd  = (float*)(smem + OFF_SD);

    const int tid  = threadIdx.x;
    const int wid  = tid >> 5;
    const int lid  = tid & 31;
    const int wrow = wid * 16;

    // ---- N-split group assignment ----
    const int gsz   = gridDim.x / NSPLIT;
    const int half  = (NSPLIT > 1) ? (blockIdx.x / gsz) : 0;
    const int nbase = half * NC;
    const int tstart = (NSPLIT > 1) ? (blockIdx.x % gsz) : blockIdx.x;
    const int tstep  = (NSPLIT > 1) ? gsz : gridDim.x;

    // ---- block prologue: B tiles (transpose + split), Wa_pos, bias ----
    const float* Wp = Wa + (size_t)cin * H;
    for (int t = tid; t < 3 * H; t += TH) sWp[t] = Wp[t];
    for (int t = tid; t < NC;    t += TH) sbb[t] = bb[nbase + t];
    for (int t = tid; t < NC * H; t += TH) {
        int n = t / H, k = t % H;
        float v = Wb[(size_t)k * nout + nbase + n];
        __nv_bfloat16 h = __float2bfloat16(v);
        __nv_bfloat16 l = __float2bfloat16(v - __bfloat162float(h));
        *(__nv_bfloat16*)(smem + OFF_BH + (n * SA + k) * 2) = h;
        *(__nv_bfloat16*)(smem + OFF_BL + (n * SA + k) * 2) = l;
    }

    const int lm = lid >> 3, lr = lid & 7;
    const int a_row_off = (lm & 1) * 8 + lr;   // + k-block (lm>>1)*8
    const int b_row_off = (lm >> 1) * 8 + lr;  // + k-block (lm&1)*8
    const int NT = (NEDGES + EP - 1) / EP;

    for (int tile = tstart; tile < NT; tile += tstep) {
        const int ebase = tile * EP;

        // ---- pass 1: per-edge src index + dpos ----
        if (tid < EP) {
            const int ge = ebase + tid;
            int j = -1;
            float d0 = 0.f, d1 = 0.f, d2 = 0.f;
            if (ge < NEDGES) {
                const int i = ge / KNN;
                j = __ldg(&src[ge]);
                d0 = __ldg(&pos[3 * j + 0]) - __ldg(&pos[3 * i + 0]);
                d1 = __ldg(&pos[3 * j + 1]) - __ldg(&pos[3 * i + 1]);
                d2 = __ldg(&pos[3 * j + 2]) - __ldg(&pos[3 * i + 2]);
            }
            sj[tid] = j;
            sd[tid * 3 + 0] = d0;
            sd[tid * 3 + 1] = d1;
            sd[tid * 3 + 2] = d2;
        }
        if (tid >= EP && tid < M) sj[tid] = -1;
        __syncthreads();   // sj/sd ready AND prev epilogue done reading z

        // ---- pass 2: build A tile hi/lo in smem ----
        {
            constexpr int PPR = H / 2;   // bf16 pairs per row
            for (int idx = tid; idx < M * PPR; idx += TH) {
                const int r = idx / PPR, c = (idx % PPR) * 2;
                uint32_t hv = 0u, lv = 0u;
                const int j = sj[r];
                if (j >= 0) {
                    const float d0 = sd[r * 3], d1 = sd[r * 3 + 1], d2 = sd[r * 3 + 2];
                    const float2 yv = *(const float2*)&y[(size_t)j * H + c];
                    float v0 = yv.x, v1 = yv.y;
                    v0 = fmaf(d0, sWp[c],         v0);
                    v1 = fmaf(d0, sWp[c + 1],     v1);
                    v0 = fmaf(d1, sWp[H + c],     v0);
                    v1 = fmaf(d1, sWp[H + c + 1], v1);
                    v0 = fmaf(d2, sWp[2 * H + c],     v0);
                    v1 = fmaf(d2, sWp[2 * H + c + 1], v1);
                    v0 = fmaxf(v0, 0.f); v1 = fmaxf(v1, 0.f);
                    __nv_bfloat16 h0 = __float2bfloat16(v0);
                    __nv_bfloat16 h1 = __float2bfloat16(v1);
                    __nv_bfloat16 l0 = __float2bfloat16(v0 - __bfloat162float(h0));
                    __nv_bfloat16 l1 = __float2bfloat16(v1 - __bfloat162float(h1));
                    hv = pack_bf2(h0, h1);
                    lv = pack_bf2(l0, l1);
                }
                *(uint32_t*)(smem + OFF_AH + (r * SA + c) * 2) = hv;
                *(uint32_t*)(smem + OFF_AL + (r * SA + c) * 2) = lv;
            }
        }
        __syncthreads();

        // ---- MMA mainloop ----
        float c[NT8][4];
        #pragma unroll
        for (int t = 0; t < NT8; t++)
            #pragma unroll
            for (int q = 0; q < 4; q++) c[t][q] = 0.f;

        #pragma unroll
        for (int k0 = 0; k0 < H; k0 += 16) {
            uint32_t ah[4], al[4];
            const uint32_t a_off = ((wrow + a_row_off) * SA + k0 + (lm >> 1) * 8) * 2;
            ldm_x4(ah, sb + OFF_AH + a_off);
            ldm_x4(al, sb + OFF_AL + a_off);

            #pragma unroll
            for (int np = 0; np < NT8 / 2; np++) {
                uint32_t bh[4], bl[4];
                const uint32_t b_off = ((np * 16 + b_row_off) * SA + k0 + (lm & 1) * 8) * 2;
                ldm_x4(bh, sb + OFF_BH + b_off);
                ldm_x4(bl, sb + OFF_BL + b_off);
                mma_bf16(c[2 * np],     ah, &bh[0]);
                mma_bf16(c[2 * np],     ah, &bl[0]);
                mma_bf16(c[2 * np],     al, &bh[0]);
                mma_bf16(c[2 * np + 1], ah, &bh[2]);
                mma_bf16(c[2 * np + 1], ah, &bl[2]);
                mma_bf16(c[2 * np + 1], al, &bh[2]);
            }
        }
        __syncthreads();   // all warps done reading A before z overwrites it

        // ---- store C frags to z ----
        {
            const int qr = lid >> 2, qc = (lid & 3) * 2;
            #pragma unroll
            for (int t = 0; t < NT8; t++) {
                float* zp = z + (wrow + qr) * NP + t * 8 + qc;
                zp[0] = c[t][0];
                zp[1] = c[t][1];
                zp[8 * NP]     = c[t][2];
                zp[8 * NP + 1] = c[t][3];
            }
        }
        __syncthreads();

        // ---- 6-row max + bias + relu -> out ----
        for (int t = tid; t < NODES * NC; t += TH) {
            const int g = t / NC, col = t % NC;
            const int node = tile * NODES + g;
            if (node < NNODES) {
                const float* zp = z + (6 * g) * NP + col;
                float m = zp[0];
                m = fmaxf(m, zp[NP]);
                m = fmaxf(m, zp[2 * NP]);
                m = fmaxf(m, zp[3 * NP]);
                m = fmaxf(m, zp[4 * NP]);
                m = fmaxf(m, zp[5 * NP]);
                out[(size_t)node * nout + nbase + col] = fmaxf(m + sbb[col], 0.f);
            }
        }
    }
}

template<int H, int NC, int TH>
static constexpr int smemF() {
    constexpr int M  = 16 * (TH / 32);
    constexpr int SA = H + 8;
    return 2 * M * SA * 2        // A hi/lo
         + 2 * NC * SA * 2       // B hi/lo
         + 3 * H * 4             // Wa_pos
         + NC * 4                // bias
         + M * 4                 // sj
         + M * 3 * 4 + 64;       // sd + slack
}

// ---------------- host ----------------
extern "C" void kernel_launch(void* const* d_in, const int* in_sizes, int n_in,
                              void* d_out, int out_size)
{
    const float* pos = (const float*)d_in[0];
    const int*   src = (const int*)d_in[1];   // row 0 of edge_index
    const float* W1a = (const float*)d_in[2];
    const float* b1a = (const float*)d_in[3];
    const float* W1b = (const float*)d_in[4];
    const float* b1b = (const float*)d_in[5];
    const float* W2a = (const float*)d_in[6];
    const float* b2a = (const float*)d_in[7];
    const float* W2b = (const float*)d_in[8];
    const float* b2b = (const float*)d_in[9];
    const float* W3a = (const float*)d_in[10];
    const float* b3a = (const float*)d_in[11];
    const float* W3b = (const float*)d_in[12];
    const float* b3b = (const float*)d_in[13];
    float* out = (float*)d_out;

    float *y, *h1, *h2;
    cudaGetSymbolAddress((void**)&y,  g_y);
    cudaGetSymbolAddress((void**)&h1, g_h1);
    cudaGetSymbolAddress((void**)&h2, g_h2);

    constexpr int S1 = smemF<32, 32, 512>();    // ~51 KB
    constexpr int S2 = smemF<64, 64, 512>();    // ~97 KB
    constexpr int S3 = smemF<128, 64, 256>();   // ~108 KB
    cudaFuncSetAttribute(stage2F<32, 32, 512, 1>,  cudaFuncAttributeMaxDynamicSharedMemorySize, S1);
    cudaFuncSetAttribute(stage2F<64, 64, 512, 1>,  cudaFuncAttributeMaxDynamicSharedMemorySize, S2);
    cudaFuncSetAttribute(stage2F<128, 64, 256, 2>, cudaFuncAttributeMaxDynamicSharedMemorySize, S3);

    // ---- layer 1: pos(3) -> 32 ----
    kernelN<3, 32><<<784, 256>>>(pos, W1a, b1a, y);
    stage2F<32, 32, 512, 1><<<296, 512, S1>>>(y, pos, src, W1a, 3, W1b, b1b, 32, h1);

    // ---- layer 2: 32 -> 64 ----
    kernelN<32, 64><<<784, 256>>>(h1, W2a, b2a, y);
    stage2F<64, 64, 512, 1><<<296, 512, S2>>>(y, pos, src, W2a, 32, W2b, b2b, 64, h2);

    // ---- layer 3: 64 -> 128 ----
    kernelN<64, 128><<<784, 256>>>(h2, W3a, b3a, y);
    stage2F<128, 64, 256, 2><<<296, 256, S3>>>(y, pos, src, W3a, 64, W3b, b3b, 128, out);
}

// round 7
// speedup vs baseline: 1.1889x; 1.1889x over previous
#include <cuda_runtime.h>
#include <cuda_bf16.h>
#include <stdint.h>

#define NNODES 100000
#define KNN 6
#define NEDGES 600000

// ---------------- device scratch (no allocation allowed) ----------------
__device__ float g_y [(size_t)NNODES * 128];   // node-level partial (x@Wa_top + ba)
__device__ float g_h1[(size_t)NNODES * 32];
__device__ float g_h2[(size_t)NNODES * 64];

// ---------------- PTX helpers (sm_80+: mma.sync / ldmatrix) ----------------
__device__ __forceinline__ uint32_t s2u(const void* p) {
    uint32_t a;
    asm("{ .reg .u64 t; cvta.to.shared.u64 t, %1; cvt.u32.u64 %0, t; }" : "=r"(a) : "l"(p));
    return a;
}
__device__ __forceinline__ void ldm_x4(uint32_t* r, uint32_t addr) {
    asm volatile("ldmatrix.sync.aligned.m8n8.x4.shared.b16 {%0,%1,%2,%3}, [%4];"
                 : "=r"(r[0]), "=r"(r[1]), "=r"(r[2]), "=r"(r[3]) : "r"(addr));
}
__device__ __forceinline__ void mma_bf16(float* c, const uint32_t* a, const uint32_t* b) {
    asm volatile("mma.sync.aligned.m16n8k16.row.col.f32.bf16.bf16.f32 "
                 "{%0,%1,%2,%3}, {%4,%5,%6,%7}, {%8,%9}, {%0,%1,%2,%3};"
                 : "+f"(c[0]), "+f"(c[1]), "+f"(c[2]), "+f"(c[3])
                 : "r"(a[0]), "r"(a[1]), "r"(a[2]), "r"(a[3]), "r"(b[0]), "r"(b[1]));
}
__device__ __forceinline__ uint32_t pack_bf2(__nv_bfloat16 a, __nv_bfloat16 b) {
    __nv_bfloat162 v = __halves2bfloat162(a, b);
    return *(uint32_t*)&v;
}

// ============ kernelN: y[node] = x @ Wa_top + ba  (warp per node) ============
template<int CIN, int H>
__global__ __launch_bounds__(256) void kernelN(const float* __restrict__ x,
                                               const float* __restrict__ Wa,
                                               const float* __restrict__ ba,
                                               float* __restrict__ y)
{
    constexpr int CPL = H / 32;
    __shared__ float sW[CIN * H];
    __shared__ float sb[H];
    for (int t = threadIdx.x; t < CIN * H; t += 256) sW[t] = Wa[t];
    for (int t = threadIdx.x; t < H;       t += 256) sb[t] = ba[t];
    __syncthreads();

    const int lane = threadIdx.x & 31;
    const int gw = (blockIdx.x * 256 + threadIdx.x) >> 5;
    const int nw = (gridDim.x * 256) >> 5;
    const int c0 = lane * CPL;

    for (int node = gw; node < NNODES; node += nw) {
        float acc[CPL];
        #pragma unroll
        for (int q = 0; q < CPL; q++) acc[q] = sb[c0 + q];
        #pragma unroll 4
        for (int c = 0; c < CIN; c++) {
            float xv = __ldg(&x[(size_t)node * CIN + c]);
            #pragma unroll
            for (int q = 0; q < CPL; q++) acc[q] = fmaf(xv, sW[c * H + c0 + q], acc[q]);
        }
        #pragma unroll
        for (int q = 0; q < CPL; q++) y[(size_t)node * H + c0 + q] = acc[q];
    }
}

// ============ fused stage2F ============
// M = 16*(TH/32) rows; EP = floor(M/6)*6 real edges per tile; warp w owns rows
// [16w,16w+16). A tile built in-kernel: hid[e] = relu(y[src[e]] + dpos @ Wa_pos),
// split to bf16 hi+lo. Build loop is column-pair-fixed per thread (Wa_pos in regs).
// C = Ah*Bh + Ah*Bl + Al*Bh (fp32 accum). z aliases A region.
template<int H, int N, int TH, int MINB>
__global__ __launch_bounds__(TH, MINB) void stage2F(const float* __restrict__ y,
                                                    const float* __restrict__ pos,
                                                    const int*   __restrict__ src,
                                                    const float* __restrict__ Wa,  // [(cin+3)][H]
                                                    int cin,
                                                    const float* __restrict__ Wb,  // [H][N]
                                                    const float* __restrict__ bb,
                                                    float* __restrict__ out)
{
    constexpr int M     = 16 * (TH / 32);
    constexpr int EP    = (M / KNN) * KNN;
    constexpr int NODES = M / KNN;
    constexpr int SA    = H + 8;           // padded A/B row stride (bf16)
    constexpr int NP    = N + 4;           // padded z row (floats)
    constexpr int NT8   = N / 8;
    constexpr int PPR   = H / 2;           // column pairs per row
    constexpr int RS    = TH / PPR;        // row stride in build loop
    constexpr int OFF_AH = 0;
    constexpr int OFF_AL = M * SA * 2;
    constexpr int OFF_BH = 2 * M * SA * 2;
    constexpr int OFF_BL = OFF_BH + N * SA * 2;
    constexpr int OFF_WP = OFF_BL + N * SA * 2;        // 3*H floats
    constexpr int OFF_BB = OFF_WP + 3 * H * 4;         // N floats
    constexpr int OFF_SJ = OFF_BB + N * 4;             // M ints
    constexpr int OFF_SD = OFF_SJ + M * 4;             // EP*3 floats

    extern __shared__ char smem[];
    const uint32_t sb = s2u(smem);
    float* z   = (float*)smem;             // aliases A region (NP <= SA)
    float* sWp = (float*)(smem + OFF_WP);
    float* sbb = (float*)(smem + OFF_BB);
    int*   sj  = (int*)  (smem + OFF_SJ);
    float* sd  = (float*)(smem + OFF_SD);

    const int tid  = threadIdx.x;
    const int wid  = tid >> 5;
    const int lid  = tid & 31;
    const int wrow = wid * 16;

    // ---- block prologue: B tiles (transpose + split), Wa_pos, bias ----
    const float* Wp = Wa + (size_t)cin * H;
    for (int t = tid; t < 3 * H; t += TH) sWp[t] = Wp[t];
    for (int t = tid; t < N;     t += TH) sbb[t] = bb[t];
    for (int t = tid; t < N * H; t += TH) {
        int n = t / H, k = t % H;
        float v = Wb[(size_t)k * N + n];
        __nv_bfloat16 h = __float2bfloat16(v);
        __nv_bfloat16 l = __float2bfloat16(v - __bfloat162float(h));
        *(__nv_bfloat16*)(smem + OFF_BH + (n * SA + k) * 2) = h;
        *(__nv_bfloat16*)(smem + OFF_BL + (n * SA + k) * 2) = l;
    }
    __syncthreads();

    // ---- hoist this thread's 6 Wa_pos values into registers ----
    const int cp = tid % PPR;          // fixed column pair for build loop
    const int rt = tid / PPR;          // starting row
    const float w0a = sWp[2 * cp],         w0b = sWp[2 * cp + 1];
    const float w1a = sWp[H + 2 * cp],     w1b = sWp[H + 2 * cp + 1];
    const float w2a = sWp[2 * H + 2 * cp], w2b = sWp[2 * H + 2 * cp + 1];

    const int lm = lid >> 3, lr = lid & 7;
    const int a_row_off = (lm & 1) * 8 + lr;   // + k-block (lm>>1)*8
    const int b_row_off = (lm >> 1) * 8 + lr;  // + k-block (lm&1)*8
    const int NT = (NEDGES + EP - 1) / EP;

    for (int tile = blockIdx.x; tile < NT; tile += gridDim.x) {
        const int ebase = tile * EP;

        // ---- pass 1: per-edge src index + dpos ----
        if (tid < EP) {
            const int ge = ebase + tid;
            int j = -1;
            float d0 = 0.f, d1 = 0.f, d2 = 0.f;
            if (ge < NEDGES) {
                const int i = ge / KNN;
                j = __ldg(&src[ge]);
                d0 = __ldg(&pos[3 * j + 0]) - __ldg(&pos[3 * i + 0]);
                d1 = __ldg(&pos[3 * j + 1]) - __ldg(&pos[3 * i + 1]);
                d2 = __ldg(&pos[3 * j + 2]) - __ldg(&pos[3 * i + 2]);
            }
            sj[tid] = j;
            sd[tid * 3 + 0] = d0;
            sd[tid * 3 + 1] = d1;
            sd[tid * 3 + 2] = d2;
        }
        if (tid >= EP && tid < M) sj[tid] = -1;
        __syncthreads();   // sj/sd ready AND prev epilogue done reading z

        // ---- pass 2: build A tile hi/lo (column-fixed threads) ----
        #pragma unroll 4
        for (int r = rt; r < M; r += RS) {
            uint32_t hv = 0u, lv = 0u;
            const int j = sj[r];
            if (j >= 0) {
                const float d0 = sd[r * 3], d1 = sd[r * 3 + 1], d2 = sd[r * 3 + 2];
                const float2 yv = *(const float2*)&y[(size_t)j * H + 2 * cp];
                float v0 = fmaf(d0, w0a, fmaf(d1, w1a, fmaf(d2, w2a, yv.x)));
                float v1 = fmaf(d0, w0b, fmaf(d1, w1b, fmaf(d2, w2b, yv.y)));
                v0 = fmaxf(v0, 0.f); v1 = fmaxf(v1, 0.f);
                __nv_bfloat16 h0 = __float2bfloat16(v0);
                __nv_bfloat16 h1 = __float2bfloat16(v1);
                __nv_bfloat16 l0 = __float2bfloat16(v0 - __bfloat162float(h0));
                __nv_bfloat16 l1 = __float2bfloat16(v1 - __bfloat162float(h1));
                hv = pack_bf2(h0, h1);
                lv = pack_bf2(l0, l1);
            }
            *(uint32_t*)(smem + OFF_AH + (r * SA + 2 * cp) * 2) = hv;
            *(uint32_t*)(smem + OFF_AL + (r * SA + 2 * cp) * 2) = lv;
        }
        __syncthreads();

        // ---- MMA mainloop ----
        float c[NT8][4];
        #pragma unroll
        for (int t = 0; t < NT8; t++)
            #pragma unroll
            for (int q = 0; q < 4; q++) c[t][q] = 0.f;

        #pragma unroll
        for (int k0 = 0; k0 < H; k0 += 16) {
            uint32_t ah[4], al[4];
            const uint32_t a_off = ((wrow + a_row_off) * SA + k0 + (lm >> 1) * 8) * 2;
            ldm_x4(ah, sb + OFF_AH + a_off);
            ldm_x4(al, sb + OFF_AL + a_off);

            #pragma unroll
            for (int np = 0; np < NT8 / 2; np++) {
                uint32_t bh[4], bl[4];
                const uint32_t b_off = ((np * 16 + b_row_off) * SA + k0 + (lm & 1) * 8) * 2;
                ldm_x4(bh, sb + OFF_BH + b_off);
                ldm_x4(bl, sb + OFF_BL + b_off);
                mma_bf16(c[2 * np],     ah, &bh[0]);
                mma_bf16(c[2 * np],     ah, &bl[0]);
                mma_bf16(c[2 * np],     al, &bh[0]);
                mma_bf16(c[2 * np + 1], ah, &bh[2]);
                mma_bf16(c[2 * np + 1], ah, &bl[2]);
                mma_bf16(c[2 * np + 1], al, &bh[2]);
            }
        }
        __syncthreads();   // all warps done reading A before z overwrites it

        // ---- store C frags to z ----
        {
            const int qr = lid >> 2, qc = (lid & 3) * 2;
            #pragma unroll
            for (int t = 0; t < NT8; t++) {
                float* zp = z + (wrow + qr) * NP + t * 8 + qc;
                zp[0] = c[t][0];
                zp[1] = c[t][1];
                zp[8 * NP]     = c[t][2];
                zp[8 * NP + 1] = c[t][3];
            }
        }
        __syncthreads();

        // ---- 6-row max + bias + relu -> out ----
        for (int t = tid; t < NODES * N; t += TH) {
            const int g = t / N, col = t % N;
            const int node = tile * NODES + g;
            if (node < NNODES) {
                const float* zp = z + (6 * g) * NP + col;
                float m = zp[0];
                m = fmaxf(m, zp[NP]);
                m = fmaxf(m, zp[2 * NP]);
                m = fmaxf(m, zp[3 * NP]);
                m = fmaxf(m, zp[4 * NP]);
                m = fmaxf(m, zp[5 * NP]);
                out[(size_t)node * N + col] = fmaxf(m + sbb[col], 0.f);
            }
        }
    }
}

template<int H, int N, int TH>
static constexpr int smemF() {
    constexpr int M  = 16 * (TH / 32);
    constexpr int SA = H + 8;
    return 2 * M * SA * 2        // A hi/lo
         + 2 * N * SA * 2        // B hi/lo
         + 3 * H * 4             // Wa_pos
         + N * 4                 // bias
         + M * 4                 // sj
         + M * 3 * 4 + 64;       // sd + slack
}

// ---------------- host ----------------
extern "C" void kernel_launch(void* const* d_in, const int* in_sizes, int n_in,
                              void* d_out, int out_size)
{
    const float* pos = (const float*)d_in[0];
    const int*   src = (const int*)d_in[1];   // row 0 of edge_index
    const float* W1a = (const float*)d_in[2];
    const float* b1a = (const float*)d_in[3];
    const float* W1b = (const float*)d_in[4];
    const float* b1b = (const float*)d_in[5];
    const float* W2a = (const float*)d_in[6];
    const float* b2a = (const float*)d_in[7];
    const float* W2b = (const float*)d_in[8];
    const float* b2b = (const float*)d_in[9];
    const float* W3a = (const float*)d_in[10];
    const float* b3a = (const float*)d_in[11];
    const float* W3b = (const float*)d_in[12];
    const float* b3b = (const float*)d_in[13];
    float* out = (float*)d_out;

    float *y, *h1, *h2;
    cudaGetSymbolAddress((void**)&y,  g_y);
    cudaGetSymbolAddress((void**)&h1, g_h1);
    cudaGetSymbolAddress((void**)&h2, g_h2);

    constexpr int S1 = smemF<32, 32, 512>();     // ~49 KB   (2 CTAs/SM)
    constexpr int S2 = smemF<64, 64, 512>();     // ~116 KB  (2 CTAs/SM)
    constexpr int S3 = smemF<128, 128, 512>();   // ~215 KB  (1 CTA/SM)
    cudaFuncSetAttribute(stage2F<32, 32, 512, 2>,   cudaFuncAttributeMaxDynamicSharedMemorySize, S1);
    cudaFuncSetAttribute(stage2F<64, 64, 512, 2>,   cudaFuncAttributeMaxDynamicSharedMemorySize, S2);
    cudaFuncSetAttribute(stage2F<128, 128, 512, 1>, cudaFuncAttributeMaxDynamicSharedMemorySize, S3);

    // ---- layer 1: pos(3) -> 32 ----
    kernelN<3, 32><<<784, 256>>>(pos, W1a, b1a, y);
    stage2F<32, 32, 512, 2><<<296, 512, S1>>>(y, pos, src, W1a, 3, W1b, b1b, h1);

    // ---- layer 2: 32 -> 64 ----
    kernelN<32, 64><<<784, 256>>>(h1, W2a, b2a, y);
    stage2F<64, 64, 512, 2><<<296, 512, S2>>>(y, pos, src, W2a, 32, W2b, b2b, h2);

    // ---- layer 3: 64 -> 128 ----
    kernelN<64, 128><<<784, 256>>>(h2, W3a, b3a, y);
    stage2F<128, 128, 512, 1><<<148, 512, S3>>>(y, pos, src, W3a, 64, W3b, b3b, out);
}

// round 8
// speedup vs baseline: 1.5124x; 1.2721x over previous
#include <cuda_runtime.h>
#include <cuda_fp16.h>
#include <stdint.h>

#define NNODES 100000
#define KNN 6
#define NEDGES 600000

// ---------------- device scratch (no allocation allowed) ----------------
__device__ float g_y [(size_t)NNODES * 128];   // node-level partial (x@Wa_top + ba)
__device__ float g_h1[(size_t)NNODES * 32];
__device__ float g_h2[(size_t)NNODES * 64];

// ---------------- PTX helpers (sm_80+: mma.sync / ldmatrix) ----------------
__device__ __forceinline__ uint32_t s2u(const void* p) {
    uint32_t a;
    asm("{ .reg .u64 t; cvta.to.shared.u64 t, %1; cvt.u32.u64 %0, t; }" : "=r"(a) : "l"(p));
    return a;
}
__device__ __forceinline__ void ldm_x4(uint32_t* r, uint32_t addr) {
    asm volatile("ldmatrix.sync.aligned.m8n8.x4.shared.b16 {%0,%1,%2,%3}, [%4];"
                 : "=r"(r[0]), "=r"(r[1]), "=r"(r[2]), "=r"(r[3]) : "r"(addr));
}
__device__ __forceinline__ void mma_f16(float* c, const uint32_t* a, const uint32_t* b) {
    asm volatile("mma.sync.aligned.m16n8k16.row.col.f32.f16.f16.f32 "
                 "{%0,%1,%2,%3}, {%4,%5,%6,%7}, {%8,%9}, {%0,%1,%2,%3};"
                 : "+f"(c[0]), "+f"(c[1]), "+f"(c[2]), "+f"(c[3])
                 : "r"(a[0]), "r"(a[1]), "r"(a[2]), "r"(a[3]), "r"(b[0]), "r"(b[1]));
}
__device__ __forceinline__ uint32_t pack_h2(float a, float b) {
    __half2 v = __floats2half2_rn(a, b);
    return *(uint32_t*)&v;
}

// ============ kernelN: y[node] = x @ Wa_top + ba  (warp per node) ============
template<int CIN, int H>
__global__ __launch_bounds__(256) void kernelN(const float* __restrict__ x,
                                               const float* __restrict__ Wa,
                                               const float* __restrict__ ba,
                                               float* __restrict__ y)
{
    constexpr int CPL = H / 32;
    __shared__ float sW[CIN * H];
    __shared__ float sb[H];
    for (int t = threadIdx.x; t < CIN * H; t += 256) sW[t] = Wa[t];
    for (int t = threadIdx.x; t < H;       t += 256) sb[t] = ba[t];
    __syncthreads();

    const int lane = threadIdx.x & 31;
    const int gw = (blockIdx.x * 256 + threadIdx.x) >> 5;
    const int nw = (gridDim.x * 256) >> 5;
    const int c0 = lane * CPL;

    for (int node = gw; node < NNODES; node += nw) {
        float acc[CPL];
        #pragma unroll
        for (int q = 0; q < CPL; q++) acc[q] = sb[c0 + q];
        #pragma unroll 4
        for (int c = 0; c < CIN; c++) {
            float xv = __ldg(&x[(size_t)node * CIN + c]);
            #pragma unroll
            for (int q = 0; q < CPL; q++) acc[q] = fmaf(xv, sW[c * H + c0 + q], acc[q]);
        }
        #pragma unroll
        for (int q = 0; q < CPL; q++) y[(size_t)node * H + c0 + q] = acc[q];
    }
}

// ============ fused stage2F (single-term fp16 MMA) ============
// M = 16*(TH/32) rows; EP = floor(M/6)*6 real edges; warp w owns rows [16w,16w+16).
// A tile built in-kernel: hid[e] = relu(y[src[e]] + dpos @ Wa_pos) -> fp16.
// z (fp16, row stride N+8 = SA) aliases the A region exactly.
template<int H, int N, int TH, int MINB>
__global__ __launch_bounds__(TH, MINB) void stage2F(const float* __restrict__ y,
                                                    const float* __restrict__ pos,
                                                    const int*   __restrict__ src,
                                                    const float* __restrict__ Wa,  // [(cin+3)][H]
                                                    int cin,
                                                    const float* __restrict__ Wb,  // [H][N]
                                                    const float* __restrict__ bb,
                                                    float* __restrict__ out)
{
    constexpr int M     = 16 * (TH / 32);
    constexpr int EP    = (M / KNN) * KNN;
    constexpr int NODES = M / KNN;
    constexpr int SA    = H + 8;           // padded A/B row stride (halfs)
    constexpr int NPh   = N + 8;           // padded z row (halfs); NPh == SA when H==N
    constexpr int NT8   = N / 8;
    constexpr int PPR   = H / 2;           // column pairs per row
    constexpr int RS    = TH / PPR;        // row stride in build loop
    constexpr int OFF_A  = 0;
    constexpr int OFF_B  = M * SA * 2;
    constexpr int OFF_WP = OFF_B + N * SA * 2;         // 3*H floats
    constexpr int OFF_BB = OFF_WP + 3 * H * 4;         // N floats
    constexpr int OFF_SJ = OFF_BB + N * 4;             // M ints
    constexpr int OFF_SD = OFF_SJ + M * 4;             // M*3 floats

    extern __shared__ char smem[];
    const uint32_t sb = s2u(smem);
    __half* z  = (__half*)smem;            // aliases A region (M*NPh*2 <= M*SA*2)
    float* sWp = (float*)(smem + OFF_WP);
    float* sbb = (float*)(smem + OFF_BB);
    int*   sj  = (int*)  (smem + OFF_SJ);
    float* sd  = (float*)(smem + OFF_SD);

    const int tid  = threadIdx.x;
    const int wid  = tid >> 5;
    const int lid  = tid & 31;
    const int wrow = wid * 16;

    // ---- block prologue: B tile (transpose, fp16), Wa_pos, bias ----
    const float* Wp = Wa + (size_t)cin * H;
    for (int t = tid; t < 3 * H; t += TH) sWp[t] = Wp[t];
    for (int t = tid; t < N;     t += TH) sbb[t] = bb[t];
    for (int t = tid; t < N * H; t += TH) {
        int n = t / H, k = t % H;
        *(__half*)(smem + OFF_B + (n * SA + k) * 2) = __float2half_rn(Wb[(size_t)k * N + n]);
    }
    __syncthreads();

    // ---- hoist this thread's 6 Wa_pos values into registers ----
    const int cp = tid % PPR;          // fixed column pair for build loop
    const int rt = tid / PPR;          // starting row
    const float w0a = sWp[2 * cp],         w0b = sWp[2 * cp + 1];
    const float w1a = sWp[H + 2 * cp],     w1b = sWp[H + 2 * cp + 1];
    const float w2a = sWp[2 * H + 2 * cp], w2b = sWp[2 * H + 2 * cp + 1];

    const int lm = lid >> 3, lr = lid & 7;
    const int a_row_off = (lm & 1) * 8 + lr;   // + k-block (lm>>1)*8
    const int b_row_off = (lm >> 1) * 8 + lr;  // + k-block (lm&1)*8
    const int NT = (NEDGES + EP - 1) / EP;

    for (int tile = blockIdx.x; tile < NT; tile += gridDim.x) {
        const int ebase = tile * EP;

        // ---- pass 1: per-edge src index + dpos ----
        if (tid < EP) {
            const int ge = ebase + tid;
            int j = -1;
            float d0 = 0.f, d1 = 0.f, d2 = 0.f;
            if (ge < NEDGES) {
                const int i = ge / KNN;
                j = __ldg(&src[ge]);
                d0 = __ldg(&pos[3 * j + 0]) - __ldg(&pos[3 * i + 0]);
                d1 = __ldg(&pos[3 * j + 1]) - __ldg(&pos[3 * i + 1]);
                d2 = __ldg(&pos[3 * j + 2]) - __ldg(&pos[3 * i + 2]);
            }
            sj[tid] = j;
            sd[tid * 3 + 0] = d0;
            sd[tid * 3 + 1] = d1;
            sd[tid * 3 + 2] = d2;
        }
        if (tid >= EP && tid < M) sj[tid] = -1;
        __syncthreads();   // sj/sd ready AND prev epilogue done reading z

        // ---- pass 2: build A tile (fp16, column-fixed threads) ----
        #pragma unroll 4
        for (int r = rt; r < M; r += RS) {
            uint32_t hv = 0u;
            const int j = sj[r];
            if (j >= 0) {
                const float d0 = sd[r * 3], d1 = sd[r * 3 + 1], d2 = sd[r * 3 + 2];
                const float2 yv = *(const float2*)&y[(size_t)j * H + 2 * cp];
                float v0 = fmaf(d0, w0a, fmaf(d1, w1a, fmaf(d2, w2a, yv.x)));
                float v1 = fmaf(d0, w0b, fmaf(d1, w1b, fmaf(d2, w2b, yv.y)));
                hv = pack_h2(fmaxf(v0, 0.f), fmaxf(v1, 0.f));
            }
            *(uint32_t*)(smem + OFF_A + (r * SA + 2 * cp) * 2) = hv;
        }
        __syncthreads();

        // ---- MMA mainloop: C = A @ B^T, fp16 inputs, fp32 accum ----
        float c[NT8][4];
        #pragma unroll
        for (int t = 0; t < NT8; t++)
            #pragma unroll
            for (int q = 0; q < 4; q++) c[t][q] = 0.f;

        #pragma unroll
        for (int k0 = 0; k0 < H; k0 += 16) {
            uint32_t a[4];
            const uint32_t a_off = ((wrow + a_row_off) * SA + k0 + (lm >> 1) * 8) * 2;
            ldm_x4(a, sb + OFF_A + a_off);

            #pragma unroll
            for (int np = 0; np < NT8 / 2; np++) {
                uint32_t b[4];
                const uint32_t b_off = ((np * 16 + b_row_off) * SA + k0 + (lm & 1) * 8) * 2;
                ldm_x4(b, sb + OFF_B + b_off);
                mma_f16(c[2 * np],     a, &b[0]);
                mma_f16(c[2 * np + 1], a, &b[2]);
            }
        }
        __syncthreads();   // all warps done reading A before z overwrites it

        // ---- store C frags to z (fp16) ----
        {
            const int qr = lid >> 2, qc = (lid & 3) * 2;
            #pragma unroll
            for (int t = 0; t < NT8; t++) {
                *(uint32_t*)&z[(wrow + qr) * NPh + t * 8 + qc]     = pack_h2(c[t][0], c[t][1]);
                *(uint32_t*)&z[(wrow + qr + 8) * NPh + t * 8 + qc] = pack_h2(c[t][2], c[t][3]);
            }
        }
        __syncthreads();

        // ---- 6-row max + bias + relu -> out ----
        for (int t = tid; t < NODES * N; t += TH) {
            const int g = t / N, col = t % N;
            const int node = tile * NODES + g;
            if (node < NNODES) {
                const __half* zp = z + (6 * g) * NPh + col;
                float m = __half2float(zp[0]);
                m = fmaxf(m, __half2float(zp[NPh]));
                m = fmaxf(m, __half2float(zp[2 * NPh]));
                m = fmaxf(m, __half2float(zp[3 * NPh]));
                m = fmaxf(m, __half2float(zp[4 * NPh]));
                m = fmaxf(m, __half2float(zp[5 * NPh]));
                out[(size_t)node * N + col] = fmaxf(m + sbb[col], 0.f);
            }
        }
    }
}

template<int H, int N, int TH>
static constexpr int smemF() {
    constexpr int M  = 16 * (TH / 32);
    constexpr int SA = H + 8;
    return M * SA * 2            // A (z aliases)
         + N * SA * 2            // B
         + 3 * H * 4             // Wa_pos
         + N * 4                 // bias
         + M * 4                 // sj
         + M * 3 * 4 + 64;       // sd + slack
}

// ---------------- host ----------------
extern "C" void kernel_launch(void* const* d_in, const int* in_sizes, int n_in,
                              void* d_out, int out_size)
{
    const float* pos = (const float*)d_in[0];
    const int*   src = (const int*)d_in[1];   // row 0 of edge_index
    const float* W1a = (const float*)d_in[2];
    const float* b1a = (const float*)d_in[3];
    const float* W1b = (const float*)d_in[4];
    const float* b1b = (const float*)d_in[5];
    const float* W2a = (const float*)d_in[6];
    const float* b2a = (const float*)d_in[7];
    const float* W2b = (const float*)d_in[8];
    const float* b2b = (const float*)d_in[9];
    const float* W3a = (const float*)d_in[10];
    const float* b3a = (const float*)d_in[11];
    const float* W3b = (const float*)d_in[12];
    const float* b3b = (const float*)d_in[13];
    float* out = (float*)d_out;

    float *y, *h1, *h2;
    cudaGetSymbolAddress((void**)&y,  g_y);
    cudaGetSymbolAddress((void**)&h1, g_h1);
    cudaGetSymbolAddress((void**)&h2, g_h2);

    constexpr int S1 = smemF<32, 32, 512>();     // ~27 KB  (2 CTAs/SM)
    constexpr int S2 = smemF<64, 64, 512>();     // ~50 KB  (2 CTAs/SM)
    constexpr int S3 = smemF<128, 128, 256>();   // ~72 KB  (2 CTAs/SM)
    cudaFuncSetAttribute(stage2F<32, 32, 512, 2>,   cudaFuncAttributeMaxDynamicSharedMemorySize, S1);
    cudaFuncSetAttribute(stage2F<64, 64, 512, 2>,   cudaFuncAttributeMaxDynamicSharedMemorySize, S2);
    cudaFuncSetAttribute(stage2F<128, 128, 256, 2>, cudaFuncAttributeMaxDynamicSharedMemorySize, S3);

    // ---- layer 1: pos(3) -> 32 ----
    kernelN<3, 32><<<784, 256>>>(pos, W1a, b1a, y);
    stage2F<32, 32, 512, 2><<<296, 512, S1>>>(y, pos, src, W1a, 3, W1b, b1b, h1);

    // ---- layer 2: 32 -> 64 ----
    kernelN<32, 64><<<784, 256>>>(h1, W2a, b2a, y);
    stage2F<64, 64, 512, 2><<<296, 512, S2>>>(y, pos, src, W2a, 32, W2b, b2b, h2);

    // ---- layer 3: 64 -> 128 ----
    kernelN<64, 128><<<784, 256>>>(h2, W3a, b3a, y);
    stage2F<128, 128, 256, 2><<<296, 256, S3>>>(y, pos, src, W3a, 64, W3b, b3b, out);
}

// round 9
// speedup vs baseline: 1.8360x; 1.2140x over previous
#include <cuda_runtime.h>
#include <cuda_fp16.h>
#include <stdint.h>

#define NNODES 100000
#define KNN 6
#define NEDGES 600000

// ---------------- device scratch (no allocation allowed) ----------------
__device__ float g_y [(size_t)NNODES * 128];   // node-level partial (x@Wa_top + ba)
__device__ float g_h1[(size_t)NNODES * 32];
__device__ float g_h2[(size_t)NNODES * 64];

// ---------------- PTX helpers (sm_80+: mma.sync / ldmatrix) ----------------
__device__ __forceinline__ uint32_t s2u(const void* p) {
    uint32_t a;
    asm("{ .reg .u64 t; cvta.to.shared.u64 t, %1; cvt.u32.u64 %0, t; }" : "=r"(a) : "l"(p));
    return a;
}
__device__ __forceinline__ void ldm_x4(uint32_t* r, uint32_t addr) {
    asm volatile("ldmatrix.sync.aligned.m8n8.x4.shared.b16 {%0,%1,%2,%3}, [%4];"
                 : "=r"(r[0]), "=r"(r[1]), "=r"(r[2]), "=r"(r[3]) : "r"(addr));
}
__device__ __forceinline__ void mma_f16(float* c, const uint32_t* a, const uint32_t* b) {
    asm volatile("mma.sync.aligned.m16n8k16.row.col.f32.f16.f16.f32 "
                 "{%0,%1,%2,%3}, {%4,%5,%6,%7}, {%8,%9}, {%0,%1,%2,%3};"
                 : "+f"(c[0]), "+f"(c[1]), "+f"(c[2]), "+f"(c[3])
                 : "r"(a[0]), "r"(a[1]), "r"(a[2]), "r"(a[3]), "r"(b[0]), "r"(b[1]));
}
__device__ __forceinline__ uint32_t pack_h2(float a, float b) {
    __half2 v = __floats2half2_rn(a, b);
    return *(uint32_t*)&v;
}

// ============ kernelN: y[node] = x @ Wa_top + ba  (warp per node) ============
template<int CIN, int H>
__global__ __launch_bounds__(256) void kernelN(const float* __restrict__ x,
                                               const float* __restrict__ Wa,
                                               const float* __restrict__ ba,
                                               float* __restrict__ y)
{
    constexpr int CPL = H / 32;
    __shared__ float sW[CIN * H];
    __shared__ float sb[H];
    for (int t = threadIdx.x; t < CIN * H; t += 256) sW[t] = Wa[t];
    for (int t = threadIdx.x; t < H;       t += 256) sb[t] = ba[t];
    __syncthreads();

    const int lane = threadIdx.x & 31;
    const int gw = (blockIdx.x * 256 + threadIdx.x) >> 5;
    const int nw = (gridDim.x * 256) >> 5;
    const int c0 = lane * CPL;

    for (int node = gw; node < NNODES; node += nw) {
        float acc[CPL];
        #pragma unroll
        for (int q = 0; q < CPL; q++) acc[q] = sb[c0 + q];
        if constexpr (CIN % 4 == 0) {
            #pragma unroll 2
            for (int c = 0; c < CIN; c += 4) {
                const float4 xv = __ldg((const float4*)&x[(size_t)node * CIN + c]);
                #pragma unroll
                for (int q = 0; q < CPL; q++) {
                    acc[q] = fmaf(xv.x, sW[(c + 0) * H + c0 + q], acc[q]);
                    acc[q] = fmaf(xv.y, sW[(c + 1) * H + c0 + q], acc[q]);
                    acc[q] = fmaf(xv.z, sW[(c + 2) * H + c0 + q], acc[q]);
                    acc[q] = fmaf(xv.w, sW[(c + 3) * H + c0 + q], acc[q]);
                }
            }
        } else {
            #pragma unroll
            for (int c = 0; c < CIN; c++) {
                float xv = __ldg(&x[(size_t)node * CIN + c]);
                #pragma unroll
                for (int q = 0; q < CPL; q++) acc[q] = fmaf(xv, sW[c * H + c0 + q], acc[q]);
            }
        }
        #pragma unroll
        for (int q = 0; q < CPL; q++) y[(size_t)node * H + c0 + q] = acc[q];
    }
}

// ============ fused stage2F (single-term fp16 MMA, vectorized build/epilogue) ============
// M = 16*(TH/32) rows; EP = floor(M/6)*6 real edges; warp w owns rows [16w,16w+16).
// A tile built in-kernel: hid[e] = relu(y[src[e]] + dpos @ Wa_pos) -> fp16.
// Build: thread owns 4 fixed channels (float4 y load, one STS.64).
// z (fp16, row stride N+8) aliases the A region. Epilogue: half2 + hmax2.
template<int H, int N, int TH, int MINB>
__global__ __launch_bounds__(TH, MINB) void stage2F(const float* __restrict__ y,
                                                    const float* __restrict__ pos,
                                                    const int*   __restrict__ src,
                                                    const float* __restrict__ Wa,  // [(cin+3)][H]
                                                    int cin,
                                                    const float* __restrict__ Wb,  // [H][N]
                                                    const float* __restrict__ bb,
                                                    float* __restrict__ out)
{
    constexpr int M     = 16 * (TH / 32);
    constexpr int EP    = (M / KNN) * KNN;
    constexpr int NODES = M / KNN;
    constexpr int SA    = H + 8;           // padded A/B row stride (halfs)
    constexpr int NPh   = N + 8;           // padded z row (halfs)
    constexpr int NT8   = N / 8;
    constexpr int G4    = H / 4;           // 4-channel groups per row
    constexpr int RS4   = TH / G4;         // row stride in build loop
    constexpr int OFF_A  = 0;
    constexpr int OFF_B  = M * SA * 2;
    constexpr int OFF_WP = OFF_B + N * SA * 2;         // 3*H floats
    constexpr int OFF_BB = OFF_WP + 3 * H * 4;         // N floats
    constexpr int OFF_SJ = OFF_BB + N * 4;             // M ints
    constexpr int OFF_SD = OFF_SJ + M * 4;             // M*3 floats

    extern __shared__ char smem[];
    const uint32_t sb = s2u(smem);
    __half* z  = (__half*)smem;            // aliases A region (M*NPh*2 <= M*SA*2)
    float* sWp = (float*)(smem + OFF_WP);
    float* sbb = (float*)(smem + OFF_BB);
    int*   sj  = (int*)  (smem + OFF_SJ);
    float* sd  = (float*)(smem + OFF_SD);

    const int tid  = threadIdx.x;
    const int wid  = tid >> 5;
    const int lid  = tid & 31;
    const int wrow = wid * 16;

    // ---- block prologue: B tile (transpose, fp16), Wa_pos, bias ----
    const float* Wp = Wa + (size_t)cin * H;
    for (int t = tid; t < 3 * H; t += TH) sWp[t] = Wp[t];
    for (int t = tid; t < N;     t += TH) sbb[t] = bb[t];
    for (int t = tid; t < N * H; t += TH) {
        int n = t / H, k = t % H;
        *(__half*)(smem + OFF_B + (n * SA + k) * 2) = __float2half_rn(Wb[(size_t)k * N + n]);
    }
    __syncthreads();

    // ---- hoist this thread's 12 Wa_pos values (4 fixed channels) ----
    const int g4 = tid % G4;           // fixed channel group (cols 4g4..4g4+3)
    const int rt = tid / G4;           // starting row
    const int cb = 4 * g4;
    float w[3][4];
    #pragma unroll
    for (int d = 0; d < 3; d++)
        #pragma unroll
        for (int q = 0; q < 4; q++) w[d][q] = sWp[d * H + cb + q];

    const int lm = lid >> 3, lr = lid & 7;
    const int a_row_off = (lm & 1) * 8 + lr;   // + k-block (lm>>1)*8
    const int b_row_off = (lm >> 1) * 8 + lr;  // + k-block (lm&1)*8
    const int NT = (NEDGES + EP - 1) / EP;

    for (int tile = blockIdx.x; tile < NT; tile += gridDim.x) {
        const int ebase = tile * EP;

        // ---- pass 1: per-edge src index + dpos ----
        if (tid < EP) {
            const int ge = ebase + tid;
            int j = -1;
            float d0 = 0.f, d1 = 0.f, d2 = 0.f;
            if (ge < NEDGES) {
                const int i = ge / KNN;
                j = __ldg(&src[ge]);
                d0 = __ldg(&pos[3 * j + 0]) - __ldg(&pos[3 * i + 0]);
                d1 = __ldg(&pos[3 * j + 1]) - __ldg(&pos[3 * i + 1]);
                d2 = __ldg(&pos[3 * j + 2]) - __ldg(&pos[3 * i + 2]);
            }
            sj[tid] = j;
            sd[tid * 3 + 0] = d0;
            sd[tid * 3 + 1] = d1;
            sd[tid * 3 + 2] = d2;
        }
        if (tid >= EP && tid < M) sj[tid] = -1;
        __syncthreads();   // sj/sd ready AND prev epilogue done reading z

        // ---- pass 2: build A tile (fp16, 4 channels per thread) ----
        #pragma unroll 4
        for (int r = rt; r < M; r += RS4) {
            uint2 hv = make_uint2(0u, 0u);
            const int j = sj[r];
            if (j >= 0) {
                const float d0 = sd[r * 3], d1 = sd[r * 3 + 1], d2 = sd[r * 3 + 2];
                const float4 yv = *(const float4*)&y[(size_t)j * H + cb];
                float v0 = fmaf(d0, w[0][0], fmaf(d1, w[1][0], fmaf(d2, w[2][0], yv.x)));
                float v1 = fmaf(d0, w[0][1], fmaf(d1, w[1][1], fmaf(d2, w[2][1], yv.y)));
                float v2 = fmaf(d0, w[0][2], fmaf(d1, w[1][2], fmaf(d2, w[2][2], yv.z)));
                float v3 = fmaf(d0, w[0][3], fmaf(d1, w[1][3], fmaf(d2, w[2][3], yv.w)));
                hv.x = pack_h2(fmaxf(v0, 0.f), fmaxf(v1, 0.f));
                hv.y = pack_h2(fmaxf(v2, 0.f), fmaxf(v3, 0.f));
            }
            *(uint2*)(smem + OFF_A + (r * SA + cb) * 2) = hv;
        }
        __syncthreads();

        // ---- MMA mainloop: C = A @ B^T, fp16 inputs, fp32 accum ----
        float c[NT8][4];
        #pragma unroll
        for (int t = 0; t < NT8; t++)
            #pragma unroll
            for (int q = 0; q < 4; q++) c[t][q] = 0.f;

        #pragma unroll
        for (int k0 = 0; k0 < H; k0 += 16) {
            uint32_t a[4];
            const uint32_t a_off = ((wrow + a_row_off) * SA + k0 + (lm >> 1) * 8) * 2;
            ldm_x4(a, sb + OFF_A + a_off);

            #pragma unroll
            for (int np = 0; np < NT8 / 2; np++) {
                uint32_t b[4];
                const uint32_t b_off = ((np * 16 + b_row_off) * SA + k0 + (lm & 1) * 8) * 2;
                ldm_x4(b, sb + OFF_B + b_off);
                mma_f16(c[2 * np],     a, &b[0]);
                mma_f16(c[2 * np + 1], a, &b[2]);
            }
        }
        __syncthreads();   // all warps done reading A before z overwrites it

        // ---- store C frags to z (fp16) ----
        {
            const int qr = lid >> 2, qc = (lid & 3) * 2;
            #pragma unroll
            for (int t = 0; t < NT8; t++) {
                *(uint32_t*)&z[(wrow + qr) * NPh + t * 8 + qc]     = pack_h2(c[t][0], c[t][1]);
                *(uint32_t*)&z[(wrow + qr + 8) * NPh + t * 8 + qc] = pack_h2(c[t][2], c[t][3]);
            }
        }
        __syncthreads();

        // ---- 6-row max + bias + relu -> out (2 cols per thread, half2) ----
        for (int t = tid; t < NODES * (N / 2); t += TH) {
            const int g = t / (N / 2), c2 = (t % (N / 2)) * 2;
            const int node = tile * NODES + g;
            if (node < NNODES) {
                const __half2* zp = (const __half2*)(z + (6 * g) * NPh + c2);
                constexpr int S2 = NPh / 2;
                __half2 m = zp[0];
                m = __hmax2(m, zp[S2]);
                m = __hmax2(m, zp[2 * S2]);
                m = __hmax2(m, zp[3 * S2]);
                m = __hmax2(m, zp[4 * S2]);
                m = __hmax2(m, zp[5 * S2]);
                const float2 bf = *(const float2*)&sbb[c2];
                float2 r;
                r.x = fmaxf(__low2float(m)  + bf.x, 0.f);
                r.y = fmaxf(__high2float(m) + bf.y, 0.f);
                *(float2*)&out[(size_t)node * N + c2] = r;
            }
        }
    }
}

template<int H, int N, int TH>
static constexpr int smemF() {
    constexpr int M  = 16 * (TH / 32);
    constexpr int SA = H + 8;
    return M * SA * 2            // A (z aliases)
         + N * SA * 2            // B
         + 3 * H * 4             // Wa_pos
         + N * 4                 // bias
         + M * 4                 // sj
         + M * 3 * 4 + 64;       // sd + slack
}

// ---------------- host ----------------
extern "C" void kernel_launch(void* const* d_in, const int* in_sizes, int n_in,
                              void* d_out, int out_size)
{
    const float* pos = (const float*)d_in[0];
    const int*   src = (const int*)d_in[1];   // row 0 of edge_index
    const float* W1a = (const float*)d_in[2];
    const float* b1a = (const float*)d_in[3];
    const float* W1b = (const float*)d_in[4];
    const float* b1b = (const float*)d_in[5];
    const float* W2a = (const float*)d_in[6];
    const float* b2a = (const float*)d_in[7];
    const float* W2b = (const float*)d_in[8];
    const float* b2b = (const float*)d_in[9];
    const float* W3a = (const float*)d_in[10];
    const float* b3a = (const float*)d_in[11];
    const float* W3b = (const float*)d_in[12];
    const float* b3b = (const float*)d_in[13];
    float* out = (float*)d_out;

    float *y, *h1, *h2;
    cudaGetSymbolAddress((void**)&y,  g_y);
    cudaGetSymbolAddress((void**)&h1, g_h1);
    cudaGetSymbolAddress((void**)&h2, g_h2);

    constexpr int S1 = smemF<32, 32, 512>();     // ~27 KB  (2 CTAs/SM)
    constexpr int S2 = smemF<64, 64, 512>();     // ~50 KB  (2 CTAs/SM)
    constexpr int S3 = smemF<128, 128, 256>();   // ~72 KB  (2 CTAs/SM)
    cudaFuncSetAttribute(stage2F<32, 32, 512, 2>,   cudaFuncAttributeMaxDynamicSharedMemorySize, S1);
    cudaFuncSetAttribute(stage2F<64, 64, 512, 2>,   cudaFuncAttributeMaxDynamicSharedMemorySize, S2);
    cudaFuncSetAttribute(stage2F<128, 128, 256, 2>, cudaFuncAttributeMaxDynamicSharedMemorySize, S3);

    // ---- layer 1: pos(3) -> 32 ----
    kernelN<3, 32><<<784, 256>>>(pos, W1a, b1a, y);
    stage2F<32, 32, 512, 2><<<296, 512, S1>>>(y, pos, src, W1a, 3, W1b, b1b, h1);

    // ---- layer 2: 32 -> 64 ----
    kernelN<32, 64><<<784, 256>>>(h1, W2a, b2a, y);
    stage2F<64, 64, 512, 2><<<296, 512, S2>>>(y, pos, src, W2a, 32, W2b, b2b, h2);

    // ---- layer 3: 64 -> 128 ----
    kernelN<64, 128><<<784, 256>>>(h2, W3a, b3a, y);
    stage2F<128, 128, 256, 2><<<296, 256, S3>>>(y, pos, src, W3a, 64, W3b, b3b, out);
}

// round 10
// speedup vs baseline: 2.3275x; 1.2677x over previous
#include <cuda_runtime.h>
#include <cuda_fp16.h>
#include <stdint.h>

#define NNODES 100000
#define KNN 6
#define NEDGES 600000

// ---------------- device scratch (no allocation allowed) ----------------
__device__ __half g_y [(size_t)NNODES * 128];  // node-level partial (x@Wa_top + ba), fp16
__device__ __half g_h1[(size_t)NNODES * 32];   // layer outputs, fp16
__device__ __half g_h2[(size_t)NNODES * 64];
__device__ float4 g_ed[NEDGES];                // per-edge: (bitcast j, d0, d1, d2)

// ---------------- PTX helpers (sm_80+: mma.sync / ldmatrix) ----------------
__device__ __forceinline__ uint32_t s2u(const void* p) {
    uint32_t a;
    asm("{ .reg .u64 t; cvta.to.shared.u64 t, %1; cvt.u32.u64 %0, t; }" : "=r"(a) : "l"(p));
    return a;
}
__device__ __forceinline__ void ldm_x4(uint32_t* r, uint32_t addr) {
    asm volatile("ldmatrix.sync.aligned.m8n8.x4.shared.b16 {%0,%1,%2,%3}, [%4];"
                 : "=r"(r[0]), "=r"(r[1]), "=r"(r[2]), "=r"(r[3]) : "r"(addr));
}
__device__ __forceinline__ void mma_f16(float* c, const uint32_t* a, const uint32_t* b) {
    asm volatile("mma.sync.aligned.m16n8k16.row.col.f32.f16.f16.f32 "
                 "{%0,%1,%2,%3}, {%4,%5,%6,%7}, {%8,%9}, {%0,%1,%2,%3};"
                 : "+f"(c[0]), "+f"(c[1]), "+f"(c[2]), "+f"(c[3])
                 : "r"(a[0]), "r"(a[1]), "r"(a[2]), "r"(a[3]), "r"(b[0]), "r"(b[1]));
}
__device__ __forceinline__ uint32_t pack_h2(float a, float b) {
    __half2 v = __floats2half2_rn(a, b);
    return *(uint32_t*)&v;
}

// ============ prepE: per-edge src index + relative position (once, reused 3x) ============
__global__ __launch_bounds__(256) void prepE(const float* __restrict__ pos,
                                             const int*   __restrict__ src,
                                             float4* __restrict__ ed)
{
    for (int e = blockIdx.x * 256 + threadIdx.x; e < NEDGES; e += gridDim.x * 256) {
        const int i = e / KNN;
        const int j = __ldg(&src[e]);
        float4 v;
        v.x = __int_as_float(j);
        v.y = __ldg(&pos[3 * j + 0]) - __ldg(&pos[3 * i + 0]);
        v.z = __ldg(&pos[3 * j + 1]) - __ldg(&pos[3 * i + 1]);
        v.w = __ldg(&pos[3 * j + 2]) - __ldg(&pos[3 * i + 2]);
        ed[e] = v;
    }
}

// ============ kernelN3: layer-1 node GEMM (CIN=3, H=32), scalar, fp16 out ============
__global__ __launch_bounds__(256) void kernelN3(const float* __restrict__ x,
                                                const float* __restrict__ Wa,
                                                const float* __restrict__ ba,
                                                __half* __restrict__ y)
{
    __shared__ float sW[3 * 32];
    __shared__ float sb[32];
    for (int t = threadIdx.x; t < 3 * 32; t += 256) sW[t] = Wa[t];
    for (int t = threadIdx.x; t < 32;     t += 256) sb[t] = ba[t];
    __syncthreads();

    const int lane = threadIdx.x & 31;
    const int gw = (blockIdx.x * 256 + threadIdx.x) >> 5;
    const int nw = (gridDim.x * 256) >> 5;

    for (int node = gw; node < NNODES; node += nw) {
        const float x0 = __ldg(&x[3 * node]), x1 = __ldg(&x[3 * node + 1]), x2 = __ldg(&x[3 * node + 2]);
        float acc = sb[lane];
        acc = fmaf(x0, sW[lane], acc);
        acc = fmaf(x1, sW[32 + lane], acc);
        acc = fmaf(x2, sW[64 + lane], acc);
        y[(size_t)node * 32 + lane] = __float2half_rn(acc);
    }
}

// ============ kernelNT: node GEMM y = x @ Wa_top + ba  (fp16 tensor cores) ============
// x fp16 [NNODES][CIN], Wa fp32 [(CIN+3)][H] (top CIN rows used), y fp16 [NNODES][H].
template<int CIN, int H, int TH, int MINB>
__global__ __launch_bounds__(TH, MINB) void kernelNT(const __half* __restrict__ x,
                                                     const float* __restrict__ Wa,
                                                     const float* __restrict__ ba,
                                                     __half* __restrict__ y)
{
    constexpr int M    = 16 * (TH / 32);
    constexpr int SA   = CIN + 8;
    constexpr int NT8  = H / 8;
    constexpr int CPR8 = CIN / 8;
    constexpr int OFF_A  = 0;
    constexpr int OFF_B  = M * SA * 2;
    constexpr int OFF_BB = OFF_B + H * SA * 2;

    extern __shared__ char smem[];
    const uint32_t sb = s2u(smem);
    float* sbb = (float*)(smem + OFF_BB);

    const int tid  = threadIdx.x;
    const int wid  = tid >> 5;
    const int lid  = tid & 31;
    const int wrow = wid * 16;

    for (int t = tid; t < H * CIN; t += TH) {
        int n = t / CIN, k = t % CIN;
        *(__half*)(smem + OFF_B + (n * SA + k) * 2) = __float2half_rn(Wa[(size_t)k * H + n]);
    }
    for (int t = tid; t < H; t += TH) sbb[t] = ba[t];

    const int lm = lid >> 3, lr = lid & 7;
    const int a_row_off = (lm & 1) * 8 + lr;
    const int b_row_off = (lm >> 1) * 8 + lr;
    const int NT = (NNODES + M - 1) / M;

    for (int tile = blockIdx.x; tile < NT; tile += gridDim.x) {
        const int nbase = tile * M;
        __syncthreads();   // prev MMA reads done before A overwrite (and prologue on iter 0)

        // build A (pure fp16 copy)
        for (int t = tid; t < M * CPR8; t += TH) {
            const int r = t / CPR8, ck = t % CPR8;
            const int node = nbase + r;
            uint4 v = make_uint4(0u, 0u, 0u, 0u);
            if (node < NNODES) v = *(const uint4*)&x[(size_t)node * CIN + ck * 8];
            *(uint4*)(smem + OFF_A + (r * SA + ck * 8) * 2) = v;
        }
        __syncthreads();

        float c[NT8][4];
        #pragma unroll
        for (int t = 0; t < NT8; t++)
            #pragma unroll
            for (int q = 0; q < 4; q++) c[t][q] = 0.f;

        #pragma unroll
        for (int k0 = 0; k0 < CIN; k0 += 16) {
            uint32_t a[4];
            const uint32_t a_off = ((wrow + a_row_off) * SA + k0 + (lm >> 1) * 8) * 2;
            ldm_x4(a, sb + OFF_A + a_off);
            #pragma unroll
            for (int np = 0; np < NT8 / 2; np++) {
                uint32_t b[4];
                const uint32_t b_off = ((np * 16 + b_row_off) * SA + k0 + (lm & 1) * 8) * 2;
                ldm_x4(b, sb + OFF_B + b_off);
                mma_f16(c[2 * np],     a, &b[0]);
                mma_f16(c[2 * np + 1], a, &b[2]);
            }
        }

        // epilogue: +bias, fp16, direct global store
        {
            const int qr = lid >> 2, qc = (lid & 3) * 2;
            const int n0 = nbase + wrow + qr;
            const int n1 = n0 + 8;
            #pragma unroll
            for (int t = 0; t < NT8; t++) {
                const int col = t * 8 + qc;
                const float2 bf = *(const float2*)&sbb[col];
                if (n0 < NNODES)
                    *(uint32_t*)&y[(size_t)n0 * H + col] = pack_h2(c[t][0] + bf.x, c[t][1] + bf.y);
                if (n1 < NNODES)
                    *(uint32_t*)&y[(size_t)n1 * H + col] = pack_h2(c[t][2] + bf.x, c[t][3] + bf.y);
            }
        }
    }
}

// ============ stage2F: software-pipelined fused edge-GEMM + 6-row max ============
// Double-buffered A; MMA(t) overlaps build(t+1). z aliases A(cur). fp16 single-term MMA.
template<int H, int N, int TH, int MINB, bool OUTH>
__global__ __launch_bounds__(TH, MINB) void stage2F(const __half* __restrict__ y,
                                                    const float4* __restrict__ ed,
                                                    const float* __restrict__ Wa,  // [(cin+3)][H]
                                                    int cin,
                                                    const float* __restrict__ Wb,  // [H][N]
                                                    const float* __restrict__ bb,
                                                    void* __restrict__ outv)
{
    constexpr int M     = 16 * (TH / 32);
    constexpr int EP    = (M / KNN) * KNN;
    constexpr int NODES = M / KNN;
    constexpr int SA    = H + 8;           // padded A/B row stride (halfs); z stride too (N==H)
    constexpr int NT8   = N / 8;
    constexpr int G4    = H / 4;
    constexpr int RS4   = TH / G4;
    constexpr int AB    = M * SA * 2;      // one A buffer (bytes)
    constexpr int OFF_B  = 2 * AB;
    constexpr int OFF_WP = OFF_B + N * SA * 2;
    constexpr int OFF_BB = OFF_WP + 3 * H * 4;

    extern __shared__ char smem[];
    const uint32_t sbase = s2u(smem);
    float* sWp = (float*)(smem + OFF_WP);
    float* sbb = (float*)(smem + OFF_BB);

    const int tid  = threadIdx.x;
    const int wid  = tid >> 5;
    const int lid  = tid & 31;
    const int wrow = wid * 16;

    // ---- block prologue ----
    const float* Wp = Wa + (size_t)cin * H;
    for (int t = tid; t < 3 * H; t += TH) sWp[t] = Wp[t];
    for (int t = tid; t < N;     t += TH) sbb[t] = bb[t];
    for (int t = tid; t < N * H; t += TH) {
        int n = t / H, k = t % H;
        *(__half*)(smem + OFF_B + (n * SA + k) * 2) = __float2half_rn(Wb[(size_t)k * N + n]);
    }
    __syncthreads();

    // ---- hoist Wa_pos (4 fixed channels per thread) ----
    const int g4 = tid % G4;
    const int rt = tid / G4;
    const int cb = 4 * g4;
    float w[3][4];
    #pragma unroll
    for (int d = 0; d < 3; d++)
        #pragma unroll
        for (int q = 0; q < 4; q++) w[d][q] = sWp[d * H + cb + q];

    const int lm = lid >> 3, lr = lid & 7;
    const int a_row_off = (lm & 1) * 8 + lr;
    const int b_row_off = (lm >> 1) * 8 + lr;
    const int NT = (NEDGES + EP - 1) / EP;

    auto build = [&](int t, int buf) {
        const int ebase = t * EP;
        char* A = smem + buf * AB;
        #pragma unroll 4
        for (int r = rt; r < M; r += RS4) {
            const int ge = ebase + r;
            uint2 hv = make_uint2(0u, 0u);
            if (r < EP && ge < NEDGES) {
                const float4 e4 = __ldg(&ed[ge]);          // broadcast within G4 group
                const int j = __float_as_int(e4.x);
                const uint2 yr = *(const uint2*)&y[(size_t)j * H + cb];
                const __half2 y01 = *(const __half2*)&yr.x;
                const __half2 y23 = *(const __half2*)&yr.y;
                float v0 = __low2float(y01),  v1 = __high2float(y01);
                float v2 = __low2float(y23),  v3 = __high2float(y23);
                v0 = fmaf(e4.y, w[0][0], fmaf(e4.z, w[1][0], fmaf(e4.w, w[2][0], v0)));
                v1 = fmaf(e4.y, w[0][1], fmaf(e4.z, w[1][1], fmaf(e4.w, w[2][1], v1)));
                v2 = fmaf(e4.y, w[0][2], fmaf(e4.z, w[1][2], fmaf(e4.w, w[2][2], v2)));
                v3 = fmaf(e4.y, w[0][3], fmaf(e4.z, w[1][3], fmaf(e4.w, w[2][3], v3)));
                hv.x = pack_h2(fmaxf(v0, 0.f), fmaxf(v1, 0.f));
                hv.y = pack_h2(fmaxf(v2, 0.f), fmaxf(v3, 0.f));
            }
            *(uint2*)(A + (r * SA + cb) * 2) = hv;
        }
    };

    int cur = 0;
    if (blockIdx.x < NT) build(blockIdx.x, 0);

    for (int tile = blockIdx.x; tile < NT; tile += gridDim.x) {
        __syncthreads();   // A(cur) built; prev epilogue done reading A(nxt)

        // ---- MMA on A(cur) ----
        float c[NT8][4];
        #pragma unroll
        for (int t = 0; t < NT8; t++)
            #pragma unroll
            for (int q = 0; q < 4; q++) c[t][q] = 0.f;

        {
            const uint32_t abase = sbase + cur * AB;
            #pragma unroll
            for (int k0 = 0; k0 < H; k0 += 16) {
                uint32_t a[4];
                const uint32_t a_off = ((wrow + a_row_off) * SA + k0 + (lm >> 1) * 8) * 2;
                ldm_x4(a, abase + a_off);
                #pragma unroll
                for (int np = 0; np < NT8 / 2; np++) {
                    uint32_t b[4];
                    const uint32_t b_off = ((np * 16 + b_row_off) * SA + k0 + (lm & 1) * 8) * 2;
                    ldm_x4(b, sbase + OFF_B + b_off);
                    mma_f16(c[2 * np],     a, &b[0]);
                    mma_f16(c[2 * np + 1], a, &b[2]);
                }
            }
        }

        // ---- overlapped: build next tile into the other buffer ----
        const int nt = tile + gridDim.x;
        if (nt < NT) build(nt, cur ^ 1);
        __syncthreads();   // MMA reads of A(cur) + build writes of A(nxt) done

        // ---- store C frags to z (= A(cur) region, fp16, row stride SA) ----
        __half* z = (__half*)(smem + cur * AB);
        {
            const int qr = lid >> 2, qc = (lid & 3) * 2;
            #pragma unroll
            for (int t = 0; t < NT8; t++) {
                *(uint32_t*)&z[(wrow + qr) * SA + t * 8 + qc]     = pack_h2(c[t][0], c[t][1]);
                *(uint32_t*)&z[(wrow + qr + 8) * SA + t * 8 + qc] = pack_h2(c[t][2], c[t][3]);
            }
        }
        __syncthreads();

        // ---- 6-row max + bias + relu -> out (2 cols per thread) ----
        for (int t = tid; t < NODES * (N / 2); t += TH) {
            const int g = t / (N / 2), c2 = (t % (N / 2)) * 2;
            const int node = tile * NODES + g;
            if (node < NNODES) {
                const __half2* zp = (const __half2*)(z + (6 * g) * SA + c2);
                constexpr int S2 = SA / 2;
                __half2 m = zp[0];
                m = __hmax2(m, zp[S2]);
                m = __hmax2(m, zp[2 * S2]);
                m = __hmax2(m, zp[3 * S2]);
                m = __hmax2(m, zp[4 * S2]);
                m = __hmax2(m, zp[5 * S2]);
                const float2 bf = *(const float2*)&sbb[c2];
                const float r0 = fmaxf(__low2float(m)  + bf.x, 0.f);
                const float r1 = fmaxf(__high2float(m) + bf.y, 0.f);
                if (OUTH) {
                    *(uint32_t*)&((__half*)outv)[(size_t)node * N + c2] = pack_h2(r0, r1);
                } else {
                    *(float2*)&((float*)outv)[(size_t)node * N + c2] = make_float2(r0, r1);
                }
            }
        }
        cur ^= 1;
    }
}

template<int H, int N, int TH>
static constexpr int smemF() {
    constexpr int M  = 16 * (TH / 32);
    constexpr int SA = H + 8;
    return 2 * M * SA * 2        // A double buffer (z aliases)
         + N * SA * 2            // B
         + 3 * H * 4             // Wa_pos
         + N * 4 + 64;           // bias + slack
}
template<int CIN, int H, int TH>
static constexpr int smemN() {
    constexpr int M  = 16 * (TH / 32);
    constexpr int SA = CIN + 8;
    return M * SA * 2 + H * SA * 2 + H * 4 + 64;
}

// ---------------- host ----------------
extern "C" void kernel_launch(void* const* d_in, const int* in_sizes, int n_in,
                              void* d_out, int out_size)
{
    const float* pos = (const float*)d_in[0];
    const int*   src = (const int*)d_in[1];   // row 0 of edge_index
    const float* W1a = (const float*)d_in[2];
    const float* b1a = (const float*)d_in[3];
    const float* W1b = (const float*)d_in[4];
    const float* b1b = (const float*)d_in[5];
    const float* W2a = (const float*)d_in[6];
    const float* b2a = (const float*)d_in[7];
    const float* W2b = (const float*)d_in[8];
    const float* b2b = (const float*)d_in[9];
    const float* W3a = (const float*)d_in[10];
    const float* b3a = (const float*)d_in[11];
    const float* W3b = (const float*)d_in[12];
    const float* b3b = (const float*)d_in[13];
    float* out = (float*)d_out;

    __half *y16, *h1, *h2;
    float4* ed;
    cudaGetSymbolAddress((void**)&y16, g_y);
    cudaGetSymbolAddress((void**)&h1,  g_h1);
    cudaGetSymbolAddress((void**)&h2,  g_h2);
    cudaGetSymbolAddress((void**)&ed,  g_ed);

    constexpr int S1 = smemF<32, 32, 512>();     // ~44 KB  (2 CTAs/SM)
    constexpr int S2 = smemF<64, 64, 512>();     // ~84 KB  (2 CTAs/SM)
    constexpr int S3 = smemF<128, 128, 256>();   // ~107 KB (2 CTAs/SM)
    constexpr int SN2 = smemN<32, 64, 512>();
    constexpr int SN3 = smemN<64, 128, 256>();
    cudaFuncSetAttribute(stage2F<32, 32, 512, 2, true>,    cudaFuncAttributeMaxDynamicSharedMemorySize, S1);
    cudaFuncSetAttribute(stage2F<64, 64, 512, 2, true>,    cudaFuncAttributeMaxDynamicSharedMemorySize, S2);
    cudaFuncSetAttribute(stage2F<128, 128, 256, 2, false>, cudaFuncAttributeMaxDynamicSharedMemorySize, S3);
    cudaFuncSetAttribute(kernelNT<32, 64, 512, 2>,  cudaFuncAttributeMaxDynamicSharedMemorySize, SN2);
    cudaFuncSetAttribute(kernelNT<64, 128, 256, 2>, cudaFuncAttributeMaxDynamicSharedMemorySize, SN3);

    prepE<<<1024, 256>>>(pos, src, ed);

    // ---- layer 1: pos(3) -> 32 ----
    kernelN3<<<784, 256>>>(pos, W1a, b1a, y16);
    stage2F<32, 32, 512, 2, true><<<296, 512, S1>>>(y16, ed, W1a, 3, W1b, b1b, h1);

    // ---- layer 2: 32 -> 64 ----
    kernelNT<32, 64, 512, 2><<<296, 512, SN2>>>(h1, W2a, b2a, y16);
    stage2F<64, 64, 512, 2, true><<<296, 512, S2>>>(y16, ed, W2a, 32, W2b, b2b, h2);

    // ---- layer 3: 64 -> 128 ----
    kernelNT<64, 128, 256, 2><<<296, 256, SN3>>>(h2, W3a, b3a, y16);
    stage2F<128, 128, 256, 2, false><<<296, 256, S3>>>(y16, ed, W3a, 64, W3b, b3b, out);
}

// round 11
// speedup vs baseline: 2.4315x; 1.0447x over previous
#include <cuda_runtime.h>
#include <cuda_fp16.h>
#include <stdint.h>

#define NNODES 100000
#define KNN 6
#define NEDGES 600000

// ---------------- device scratch (no allocation allowed) ----------------
__device__ __half g_ya[(size_t)NNODES * 128];  // y ping
__device__ __half g_yb[(size_t)NNODES * 128];  // y pong
__device__ float4 g_ed[NEDGES];                // per-edge: (bitcast j, d0, d1, d2)

// ---------------- PTX helpers (sm_80+: mma.sync / ldmatrix) ----------------
__device__ __forceinline__ uint32_t s2u(const void* p) {
    uint32_t a;
    asm("{ .reg .u64 t; cvta.to.shared.u64 t, %1; cvt.u32.u64 %0, t; }" : "=r"(a) : "l"(p));
    return a;
}
__device__ __forceinline__ void ldm_x4(uint32_t* r, uint32_t addr) {
    asm volatile("ldmatrix.sync.aligned.m8n8.x4.shared.b16 {%0,%1,%2,%3}, [%4];"
                 : "=r"(r[0]), "=r"(r[1]), "=r"(r[2]), "=r"(r[3]) : "r"(addr));
}
__device__ __forceinline__ void mma_f16(float* c, const uint32_t* a, const uint32_t* b) {
    asm volatile("mma.sync.aligned.m16n8k16.row.col.f32.f16.f16.f32 "
                 "{%0,%1,%2,%3}, {%4,%5,%6,%7}, {%8,%9}, {%0,%1,%2,%3};"
                 : "+f"(c[0]), "+f"(c[1]), "+f"(c[2]), "+f"(c[3])
                 : "r"(a[0]), "r"(a[1]), "r"(a[2]), "r"(a[3]), "r"(b[0]), "r"(b[1]));
}
__device__ __forceinline__ uint32_t pack_h2(float a, float b) {
    __half2 v = __floats2half2_rn(a, b);
    return *(uint32_t*)&v;
}

// ============ prepE: per-edge (j, dpos) + layer-1 node GEMM (fused) ============
__global__ __launch_bounds__(256) void prepE(const float* __restrict__ pos,
                                             const int*   __restrict__ src,
                                             float4* __restrict__ ed,
                                             const float* __restrict__ W1a,
                                             const float* __restrict__ b1a,
                                             __half* __restrict__ y1)
{
    __shared__ float sW[3 * 32];
    __shared__ float sb[32];
    for (int t = threadIdx.x; t < 3 * 32; t += 256) sW[t] = W1a[t];
    for (int t = threadIdx.x; t < 32;     t += 256) sb[t] = b1a[t];
    __syncthreads();

    for (int e = blockIdx.x * 256 + threadIdx.x; e < NEDGES; e += gridDim.x * 256) {
        const int i = e / KNN;
        const int j = __ldg(&src[e]);
        float4 v;
        v.x = __int_as_float(j);
        v.y = __ldg(&pos[3 * j + 0]) - __ldg(&pos[3 * i + 0]);
        v.z = __ldg(&pos[3 * j + 1]) - __ldg(&pos[3 * i + 1]);
        v.w = __ldg(&pos[3 * j + 2]) - __ldg(&pos[3 * i + 2]);
        ed[e] = v;
    }

    const int lane = threadIdx.x & 31;
    const int gw = (blockIdx.x * 256 + threadIdx.x) >> 5;
    const int nw = (gridDim.x * 256) >> 5;
    for (int node = gw; node < NNODES; node += nw) {
        const float x0 = __ldg(&pos[3 * node]), x1 = __ldg(&pos[3 * node + 1]), x2 = __ldg(&pos[3 * node + 2]);
        float acc = sb[lane];
        acc = fmaf(x0, sW[lane], acc);
        acc = fmaf(x1, sW[32 + lane], acc);
        acc = fmaf(x2, sW[64 + lane], acc);
        y1[(size_t)node * 32 + lane] = __float2half_rn(acc);
    }
}

// ============ stage2F: pipelined fused edge-GEMM + 6-row max + fused next-layer node GEMM ===
// Double-buffered A; per tile the parallel section runs {edge-MMA(t), build(t+1), yMMA(t-1)}.
// Non-FINAL: epilogue writes h into smem hY only; yMMA emits y_next = h @ WaNext + baNext.
// FINAL: epilogue writes float out; no yMMA.
template<int H, int N, int H2, int TH, int MINB, bool FINAL>
__global__ __launch_bounds__(TH, MINB) void stage2F(const __half* __restrict__ y,
                                                    const float4* __restrict__ ed,
                                                    const float* __restrict__ Wa,   // [(cin+3)][H]
                                                    int cin,
                                                    const float* __restrict__ Wb,   // [H][N]
                                                    const float* __restrict__ bb,
                                                    const float* __restrict__ WaN,  // [N][H2] (top rows)
                                                    const float* __restrict__ baN,
                                                    __half* __restrict__ yN,
                                                    float* __restrict__ outF)
{
    constexpr int M     = 16 * (TH / 32);
    constexpr int EP    = (M / KNN) * KNN;
    constexpr int NODES = M / KNN;          // 42 (TH=512) or 21 (TH=256)
    constexpr int SA    = H + 8;            // A/B row stride (halfs)
    constexpr int SAY   = N + 8;            // hY/B2 row stride (halfs)
    constexpr int NT8   = N / 8;
    constexpr int G4    = H / 4;
    constexpr int RS4   = TH / G4;
    constexpr int NW    = TH / 32;
    constexpr int AB    = M * SA * 2;
    constexpr int OFF_B  = 2 * AB;
    constexpr int OFF_WP = OFF_B + N * SA * 2;
    constexpr int OFF_BB = OFF_WP + 3 * H * 4;
    constexpr int OFF_B2 = OFF_BB + N * 4;              // H2*SAY halfs (16B aligned by construction)
    constexpr int OFF_BA2= OFF_B2 + (FINAL ? 0 : H2 * SAY * 2);
    constexpr int OFF_HY = OFF_BA2 + (FINAL ? 0 : H2 * 4);

    extern __shared__ char smem[];
    const uint32_t sbase = s2u(smem);
    float* sWp = (float*)(smem + OFF_WP);
    float* sbb = (float*)(smem + OFF_BB);
    float* sba2= (float*)(smem + OFF_BA2);
    __half* hY = (__half*)(smem + OFF_HY);

    const int tid  = threadIdx.x;
    const int wid  = tid >> 5;
    const int lid  = tid & 31;
    const int wrow = wid * 16;

    // ---- block prologue ----
    const float* Wp = Wa + (size_t)cin * H;
    for (int t = tid; t < 3 * H; t += TH) sWp[t] = Wp[t];
    for (int t = tid; t < N;     t += TH) sbb[t] = bb[t];
    for (int t = tid; t < N * H; t += TH) {
        int n = t / H, k = t % H;
        *(__half*)(smem + OFF_B + (n * SA + k) * 2) = __float2half_rn(Wb[(size_t)k * N + n]);
    }
    if constexpr (!FINAL) {
        for (int t = tid; t < H2 * N; t += TH) {
            int n2 = t / N, k = t % N;
            *(__half*)(smem + OFF_B2 + (n2 * SAY + k) * 2) = __float2half_rn(WaN[(size_t)k * H2 + n2]);
        }
        for (int t = tid; t < H2; t += TH) sba2[t] = baN[t];
    }
    __syncthreads();

    // ---- hoist Wa_pos (4 fixed channels per thread) ----
    const int g4 = tid % G4;
    const int rt = tid / G4;
    const int cb = 4 * g4;
    float w[3][4];
    #pragma unroll
    for (int d = 0; d < 3; d++)
        #pragma unroll
        for (int q = 0; q < 4; q++) w[d][q] = sWp[d * H + cb + q];

    const int lm = lid >> 3, lr = lid & 7;
    const int a_row_off = (lm & 1) * 8 + lr;
    const int b_row_off = (lm >> 1) * 8 + lr;
    const int NT = (NEDGES + EP - 1) / EP;

    auto build = [&](int t, int buf) {
        const int ebase = t * EP;
        char* A = smem + buf * AB;
        #pragma unroll 4
        for (int r = rt; r < M; r += RS4) {
            const int ge = ebase + r;
            uint2 hv = make_uint2(0u, 0u);
            if (r < EP && ge < NEDGES) {
                const float4 e4 = __ldg(&ed[ge]);
                const int j = __float_as_int(e4.x);
                const uint2 yr = *(const uint2*)&y[(size_t)j * H + cb];
                const __half2 y01 = *(const __half2*)&yr.x;
                const __half2 y23 = *(const __half2*)&yr.y;
                float v0 = __low2float(y01),  v1 = __high2float(y01);
                float v2 = __low2float(y23),  v3 = __high2float(y23);
                v0 = fmaf(e4.y, w[0][0], fmaf(e4.z, w[1][0], fmaf(e4.w, w[2][0], v0)));
                v1 = fmaf(e4.y, w[0][1], fmaf(e4.z, w[1][1], fmaf(e4.w, w[2][1], v1)));
                v2 = fmaf(e4.y, w[0][2], fmaf(e4.z, w[1][2], fmaf(e4.w, w[2][2], v2)));
                v3 = fmaf(e4.y, w[0][3], fmaf(e4.z, w[1][3], fmaf(e4.w, w[2][3], v3)));
                hv.x = pack_h2(fmaxf(v0, 0.f), fmaxf(v1, 0.f));
                hv.y = pack_h2(fmaxf(v2, 0.f), fmaxf(v3, 0.f));
            }
            *(uint2*)(A + (r * SA + cb) * 2) = hv;
        }
    };

    // ---- yMMA: y_next[tile nodes] = hY @ WaNext^T + baNext ----
    auto ymma = [&](int ptile) {
        const int pbase = ptile * NODES;
        constexpr int MT = (NODES + 15) / 16;              // m-tiles over hY rows
        for (int task = wid; task < MT * (H2 / 16); task += NW) {
            const int mt = task % MT;
            const int nb = (task / MT) * 16;
            float cc[2][4] = {{0.f,0.f,0.f,0.f},{0.f,0.f,0.f,0.f}};
            #pragma unroll
            for (int k0 = 0; k0 < N; k0 += 16) {
                uint32_t a[4], b[4];
                ldm_x4(a, sbase + OFF_HY + ((mt * 16 + a_row_off) * SAY + k0 + (lm >> 1) * 8) * 2);
                ldm_x4(b, sbase + OFF_B2 + ((nb + b_row_off) * SAY + k0 + (lm & 1) * 8) * 2);
                mma_f16(cc[0], a, &b[0]);
                mma_f16(cc[1], a, &b[2]);
            }
            const int qr = lid >> 2, qc = (lid & 3) * 2;
            #pragma unroll
            for (int hh = 0; hh < 2; hh++) {
                const int col = nb + hh * 8 + qc;
                const float2 bf = *(const float2*)&sba2[col];
                const int r0 = mt * 16 + qr, r1 = r0 + 8;
                if (r0 < NODES) {
                    const int n0 = pbase + r0;
                    if (n0 < NNODES)
                        *(uint32_t*)&yN[(size_t)n0 * H2 + col] = pack_h2(cc[hh][0] + bf.x, cc[hh][1] + bf.y);
                }
                if (r1 < NODES) {
                    const int n1 = pbase + r1;
                    if (n1 < NNODES)
                        *(uint32_t*)&yN[(size_t)n1 * H2 + col] = pack_h2(cc[hh][2] + bf.x, cc[hh][3] + bf.y);
                }
            }
        }
    };

    int cur = 0;
    int prev = -1;
    if (blockIdx.x < NT) build(blockIdx.x, 0);

    for (int tile = blockIdx.x; tile < NT; tile += gridDim.x) {
        __syncthreads();   // A(cur) built; prev epilogue (hY/z reads) done

        // ---- parallel section: edge-MMA(cur) + build(next) + yMMA(prev) ----
        float c[NT8][4];
        #pragma unroll
        for (int t = 0; t < NT8; t++)
            #pragma unroll
            for (int q = 0; q < 4; q++) c[t][q] = 0.f;

        {
            const uint32_t abase = sbase + cur * AB;
            #pragma unroll
            for (int k0 = 0; k0 < H; k0 += 16) {
                uint32_t a[4];
                const uint32_t a_off = ((wrow + a_row_off) * SA + k0 + (lm >> 1) * 8) * 2;
                ldm_x4(a, abase + a_off);
                #pragma unroll
                for (int np = 0; np < NT8 / 2; np++) {
                    uint32_t b[4];
                    const uint32_t b_off = ((np * 16 + b_row_off) * SA + k0 + (lm & 1) * 8) * 2;
                    ldm_x4(b, sbase + OFF_B + b_off);
                    mma_f16(c[2 * np],     a, &b[0]);
                    mma_f16(c[2 * np + 1], a, &b[2]);
                }
            }
        }
        const int nt = tile + gridDim.x;
        if (nt < NT) build(nt, cur ^ 1);
        if constexpr (!FINAL) { if (prev >= 0) ymma(prev); }
        __syncthreads();

        // ---- store C frags to z (= A(cur) region, fp16, row stride SA) ----
        __half* z = (__half*)(smem + cur * AB);
        {
            const int qr = lid >> 2, qc = (lid & 3) * 2;
            #pragma unroll
            for (int t = 0; t < NT8; t++) {
                *(uint32_t*)&z[(wrow + qr) * SA + t * 8 + qc]     = pack_h2(c[t][0], c[t][1]);
                *(uint32_t*)&z[(wrow + qr + 8) * SA + t * 8 + qc] = pack_h2(c[t][2], c[t][3]);
            }
        }
        __syncthreads();

        // ---- 6-row max + bias + relu -> hY (or out) ----
        for (int t = tid; t < NODES * (N / 2); t += TH) {
            const int g = t / (N / 2), c2 = (t % (N / 2)) * 2;
            const int node = tile * NODES + g;
            const __half2* zp = (const __half2*)(z + (6 * g) * SA + c2);
            constexpr int S2 = SA / 2;
            __half2 m = zp[0];
            m = __hmax2(m, zp[S2]);
            m = __hmax2(m, zp[2 * S2]);
            m = __hmax2(m, zp[3 * S2]);
            m = __hmax2(m, zp[4 * S2]);
            m = __hmax2(m, zp[5 * S2]);
            const float2 bf = *(const float2*)&sbb[c2];
            const float r0 = fmaxf(__low2float(m)  + bf.x, 0.f);
            const float r1 = fmaxf(__high2float(m) + bf.y, 0.f);
            if constexpr (FINAL) {
                if (node < NNODES)
                    *(float2*)&outF[(size_t)node * N + c2] = make_float2(r0, r1);
            } else {
                hY[g * SAY + c2]     = __float2half_rn(r0);
                hY[g * SAY + c2 + 1] = __float2half_rn(r1);
            }
        }
        prev = tile;
        cur ^= 1;
    }

    if constexpr (!FINAL) {
        if (prev >= 0) {
            __syncthreads();   // final epilogue's hY writes visible
            ymma(prev);
        }
    }
}

template<int H, int N, int H2, int TH, bool FINAL>
static constexpr int smemF() {
    constexpr int M   = 16 * (TH / 32);
    constexpr int SA  = H + 8;
    constexpr int SAY = N + 8;
    int s = 2 * M * SA * 2 + N * SA * 2 + 3 * H * 4 + N * 4;
    if (!FINAL) s += H2 * SAY * 2 + H2 * 4 + 48 * SAY * 2;
    return s + 64;
}

// ---------------- host ----------------
extern "C" void kernel_launch(void* const* d_in, const int* in_sizes, int n_in,
                              void* d_out, int out_size)
{
    const float* pos = (const float*)d_in[0];
    const int*   src = (const int*)d_in[1];   // row 0 of edge_index
    const float* W1a = (const float*)d_in[2];
    const float* b1a = (const float*)d_in[3];
    const float* W1b = (const float*)d_in[4];
    const float* b1b = (const float*)d_in[5];
    const float* W2a = (const float*)d_in[6];
    const float* b2a = (const float*)d_in[7];
    const float* W2b = (const float*)d_in[8];
    const float* b2b = (const float*)d_in[9];
    const float* W3a = (const float*)d_in[10];
    const float* b3a = (const float*)d_in[11];
    const float* W3b = (const float*)d_in[12];
    const float* b3b = (const float*)d_in[13];
    float* out = (float*)d_out;

    __half *ya, *yb;
    float4* ed;
    cudaGetSymbolAddress((void**)&ya, g_ya);
    cudaGetSymbolAddress((void**)&yb, g_yb);
    cudaGetSymbolAddress((void**)&ed, g_ed);

    constexpr int S1 = smemF<32, 32, 64, 512, false>();     // ~53 KB  (2 CTAs/SM)
    constexpr int S2 = smemF<64, 64, 128, 512, false>();    // ~110 KB (2 CTAs/SM)
    constexpr int S3 = smemF<128, 128, 16, 256, true>();    // ~107 KB (2 CTAs/SM)
    cudaFuncSetAttribute(stage2F<32, 32, 64, 512, 2, false>,   cudaFuncAttributeMaxDynamicSharedMemorySize, S1);
    cudaFuncSetAttribute(stage2F<64, 64, 128, 512, 2, false>,  cudaFuncAttributeMaxDynamicSharedMemorySize, S2);
    cudaFuncSetAttribute(stage2F<128, 128, 16, 256, 2, true>,  cudaFuncAttributeMaxDynamicSharedMemorySize, S3);

    // prep: edge table + layer-1 node GEMM (y1 -> ya)
    prepE<<<1024, 256>>>(pos, src, ed, W1a, b1a, ya);

    // layer 1: edge GEMM (32) + max + fused node GEMM for layer 2 (y2 -> yb)
    stage2F<32, 32, 64, 512, 2, false><<<296, 512, S1>>>(ya, ed, W1a, 3, W1b, b1b, W2a, b2a, yb, nullptr);

    // layer 2: edge GEMM (64) + max + fused node GEMM for layer 3 (y3 -> ya)
    stage2F<64, 64, 128, 512, 2, false><<<296, 512, S2>>>(yb, ed, W2a, 32, W2b, b2b, W3a, b3a, ya, nullptr);

    // layer 3: edge GEMM (128) + max -> final out (fp32)
    stage2F<128, 128, 16, 256, 2, true><<<296, 256, S3>>>(ya, ed, W3a, 64, W3b, b3b, nullptr, nullptr, nullptr, out);
}

// round 12
// speedup vs baseline: 2.9467x; 1.2119x over previous
#include <cuda_runtime.h>
#include <cuda_fp16.h>
#include <stdint.h>

#define NNODES 100000
#define KNN 6
#define NEDGES 600000

// ---------------- device scratch (no allocation allowed) ----------------
__device__ __half g_ya[(size_t)NNODES * 128];  // y ping
__device__ __half g_yb[(size_t)NNODES * 128];  // y pong
__device__ float4 g_ed[NEDGES];                // per-edge: (bitcast j, d0, d1, d2)

// ---------------- PTX helpers (sm_80+: mma.sync / ldmatrix) ----------------
__device__ __forceinline__ uint32_t s2u(const void* p) {
    uint32_t a;
    asm("{ .reg .u64 t; cvta.to.shared.u64 t, %1; cvt.u32.u64 %0, t; }" : "=r"(a) : "l"(p));
    return a;
}
__device__ __forceinline__ void ldm_x4(uint32_t* r, uint32_t addr) {
    asm volatile("ldmatrix.sync.aligned.m8n8.x4.shared.b16 {%0,%1,%2,%3}, [%4];"
                 : "=r"(r[0]), "=r"(r[1]), "=r"(r[2]), "=r"(r[3]) : "r"(addr));
}
__device__ __forceinline__ void mma_f16(float* c, const uint32_t* a, const uint32_t* b) {
    asm volatile("mma.sync.aligned.m16n8k16.row.col.f32.f16.f16.f32 "
                 "{%0,%1,%2,%3}, {%4,%5,%6,%7}, {%8,%9}, {%0,%1,%2,%3};"
                 : "+f"(c[0]), "+f"(c[1]), "+f"(c[2]), "+f"(c[3])
                 : "r"(a[0]), "r"(a[1]), "r"(a[2]), "r"(a[3]), "r"(b[0]), "r"(b[1]));
}
__device__ __forceinline__ uint32_t pack_h2(float a, float b) {
    __half2 v = __floats2half2_rn(a, b);
    return *(uint32_t*)&v;
}

// ============ prepE: per-edge (j, dpos) + layer-1 node GEMM (fused) ============
__global__ __launch_bounds__(256) void prepE(const float* __restrict__ pos,
                                             const int*   __restrict__ src,
                                             float4* __restrict__ ed,
                                             const float* __restrict__ W1a,
                                             const float* __restrict__ b1a,
                                             __half* __restrict__ y1)
{
    __shared__ float sW[3 * 32];
    __shared__ float sb[32];
    for (int t = threadIdx.x; t < 3 * 32; t += 256) sW[t] = W1a[t];
    for (int t = threadIdx.x; t < 32;     t += 256) sb[t] = b1a[t];
    __syncthreads();

    for (int e = blockIdx.x * 256 + threadIdx.x; e < NEDGES; e += gridDim.x * 256) {
        const int i = e / KNN;
        const int j = __ldg(&src[e]);
        float4 v;
        v.x = __int_as_float(j);
        v.y = __ldg(&pos[3 * j + 0]) - __ldg(&pos[3 * i + 0]);
        v.z = __ldg(&pos[3 * j + 1]) - __ldg(&pos[3 * i + 1]);
        v.w = __ldg(&pos[3 * j + 2]) - __ldg(&pos[3 * i + 2]);
        ed[e] = v;
    }

    const int lane = threadIdx.x & 31;
    const int gw = (blockIdx.x * 256 + threadIdx.x) >> 5;
    const int nw = (gridDim.x * 256) >> 5;
    for (int node = gw; node < NNODES; node += nw) {
        const float x0 = __ldg(&pos[3 * node]), x1 = __ldg(&pos[3 * node + 1]), x2 = __ldg(&pos[3 * node + 2]);
        float acc = sb[lane];
        acc = fmaf(x0, sW[lane], acc);
        acc = fmaf(x1, sW[32 + lane], acc);
        acc = fmaf(x2, sW[64 + lane], acc);
        y1[(size_t)node * 32 + lane] = __float2half_rn(acc);
    }
}

// ============ stage2F: pipelined fused edge-GEMM + 6-row max + fused next-layer node GEMM ===
// Warp grid: WY=NWARP/WX row-warps x WX col-warps. M = 16*WY rows; each warp owns
// 16 rows x N/WX cols (32 accums/thread at the configs used). Double-buffered A;
// per tile the parallel section runs {edge-MMA(t), build(t+1), yMMA(t-1)}.
template<int H, int N, int H2, int TH, int WX, int MINB, bool FINAL>
__global__ __launch_bounds__(TH, MINB) void stage2F(const __half* __restrict__ y,
                                                    const float4* __restrict__ ed,
                                                    const float* __restrict__ Wa,   // [(cin+3)][H]
                                                    int cin,
                                                    const float* __restrict__ Wb,   // [H][N]
                                                    const float* __restrict__ bb,
                                                    const float* __restrict__ WaN,  // [N][H2] (top rows)
                                                    const float* __restrict__ baN,
                                                    __half* __restrict__ yN,
                                                    float* __restrict__ outF)
{
    constexpr int NWARP = TH / 32;
    constexpr int WY    = NWARP / WX;
    constexpr int M     = 16 * WY;
    constexpr int EP    = (M / KNN) * KNN;
    constexpr int NODES = M / KNN;
    constexpr int SA    = H + 8;            // A/B row stride (halfs)
    constexpr int SAY   = N + 8;            // hY/B2 row stride (halfs)
    constexpr int NC    = N / WX;           // cols per warp
    constexpr int NT8W  = NC / 8;
    constexpr int G4    = H / 4;
    constexpr int RS4   = TH / G4;
    constexpr int AB    = M * SA * 2;
    constexpr int OFF_B  = 2 * AB;
    constexpr int OFF_WP = OFF_B + N * SA * 2;
    constexpr int OFF_BB = OFF_WP + 3 * H * 4;
    constexpr int OFF_B2 = OFF_BB + N * 4;
    constexpr int OFF_BA2= OFF_B2 + (FINAL ? 0 : H2 * SAY * 2);
    constexpr int OFF_HY = OFF_BA2 + (FINAL ? 0 : H2 * 4);

    extern __shared__ char smem[];
    const uint32_t sbase = s2u(smem);
    float* sWp = (float*)(smem + OFF_WP);
    float* sbb = (float*)(smem + OFF_BB);
    float* sba2= (float*)(smem + OFF_BA2);
    __half* hY = (__half*)(smem + OFF_HY);

    const int tid  = threadIdx.x;
    const int wid  = tid >> 5;
    const int lid  = tid & 31;
    const int wy   = wid % WY;
    const int wx   = wid / WY;
    const int wrow = wy * 16;
    const int wcol = wx * NC;

    // ---- block prologue ----
    const float* Wp = Wa + (size_t)cin * H;
    for (int t = tid; t < 3 * H; t += TH) sWp[t] = Wp[t];
    for (int t = tid; t < N;     t += TH) sbb[t] = bb[t];
    for (int t = tid; t < N * H; t += TH) {
        int n = t / H, k = t % H;
        *(__half*)(smem + OFF_B + (n * SA + k) * 2) = __float2half_rn(Wb[(size_t)k * N + n]);
    }
    if constexpr (!FINAL) {
        for (int t = tid; t < H2 * N; t += TH) {
            int n2 = t / N, k = t % N;
            *(__half*)(smem + OFF_B2 + (n2 * SAY + k) * 2) = __float2half_rn(WaN[(size_t)k * H2 + n2]);
        }
        for (int t = tid; t < H2; t += TH) sba2[t] = baN[t];
    }
    __syncthreads();

    // ---- hoist Wa_pos (4 fixed channels per thread) ----
    const int g4 = tid % G4;
    const int rt = tid / G4;
    const int cb = 4 * g4;
    float w[3][4];
    #pragma unroll
    for (int d = 0; d < 3; d++)
        #pragma unroll
        for (int q = 0; q < 4; q++) w[d][q] = sWp[d * H + cb + q];

    const int lm = lid >> 3, lr = lid & 7;
    const int a_row_off = (lm & 1) * 8 + lr;
    const int b_row_off = (lm >> 1) * 8 + lr;
    const int NT = (NEDGES + EP - 1) / EP;

    auto build = [&](int t, int buf) {
        const int ebase = t * EP;
        char* A = smem + buf * AB;
        #pragma unroll 4
        for (int r = rt; r < M; r += RS4) {
            const int ge = ebase + r;
            uint2 hv = make_uint2(0u, 0u);
            if (r < EP && ge < NEDGES) {
                const float4 e4 = __ldg(&ed[ge]);
                const int j = __float_as_int(e4.x);
                const uint2 yr = *(const uint2*)&y[(size_t)j * H + cb];
                const __half2 y01 = *(const __half2*)&yr.x;
                const __half2 y23 = *(const __half2*)&yr.y;
                float v0 = __low2float(y01),  v1 = __high2float(y01);
                float v2 = __low2float(y23),  v3 = __high2float(y23);
                v0 = fmaf(e4.y, w[0][0], fmaf(e4.z, w[1][0], fmaf(e4.w, w[2][0], v0)));
                v1 = fmaf(e4.y, w[0][1], fmaf(e4.z, w[1][1], fmaf(e4.w, w[2][1], v1)));
                v2 = fmaf(e4.y, w[0][2], fmaf(e4.z, w[1][2], fmaf(e4.w, w[2][2], v2)));
                v3 = fmaf(e4.y, w[0][3], fmaf(e4.z, w[1][3], fmaf(e4.w, w[2][3], v3)));
                hv.x = pack_h2(fmaxf(v0, 0.f), fmaxf(v1, 0.f));
                hv.y = pack_h2(fmaxf(v2, 0.f), fmaxf(v3, 0.f));
            }
            *(uint2*)(A + (r * SA + cb) * 2) = hv;
        }
    };

    // ---- yMMA: y_next[tile nodes] = hY @ WaNext^T + baNext ----
    auto ymma = [&](int ptile) {
        const int pbase = ptile * NODES;
        constexpr int MT = (NODES + 15) / 16;
        for (int task = wid; task < MT * (H2 / 16); task += NWARP) {
            const int mt = task % MT;
            const int nb = (task / MT) * 16;
            float cc[2][4] = {{0.f,0.f,0.f,0.f},{0.f,0.f,0.f,0.f}};
            #pragma unroll
            for (int k0 = 0; k0 < N; k0 += 16) {
                uint32_t a[4], b[4];
                ldm_x4(a, sbase + OFF_HY + ((mt * 16 + a_row_off) * SAY + k0 + (lm >> 1) * 8) * 2);
                ldm_x4(b, sbase + OFF_B2 + ((nb + b_row_off) * SAY + k0 + (lm & 1) * 8) * 2);
                mma_f16(cc[0], a, &b[0]);
                mma_f16(cc[1], a, &b[2]);
            }
            const int qr = lid >> 2, qc = (lid & 3) * 2;
            #pragma unroll
            for (int hh = 0; hh < 2; hh++) {
                const int col = nb + hh * 8 + qc;
                const float2 bf = *(const float2*)&sba2[col];
                const int r0 = mt * 16 + qr, r1 = r0 + 8;
                if (r0 < NODES) {
                    const int n0 = pbase + r0;
                    if (n0 < NNODES)
                        *(uint32_t*)&yN[(size_t)n0 * H2 + col] = pack_h2(cc[hh][0] + bf.x, cc[hh][1] + bf.y);
                }
                if (r1 < NODES) {
                    const int n1 = pbase + r1;
                    if (n1 < NNODES)
                        *(uint32_t*)&yN[(size_t)n1 * H2 + col] = pack_h2(cc[hh][2] + bf.x, cc[hh][3] + bf.y);
                }
            }
        }
    };

    int cur = 0;
    int prev = -1;
    if (blockIdx.x < NT) build(blockIdx.x, 0);

    for (int tile = blockIdx.x; tile < NT; tile += gridDim.x) {
        __syncthreads();   // A(cur) built; prev epilogue (hY/z reads) done

        // ---- parallel section: edge-MMA(cur) + build(next) + yMMA(prev) ----
        float c[NT8W][4];
        #pragma unroll
        for (int t = 0; t < NT8W; t++)
            #pragma unroll
            for (int q = 0; q < 4; q++) c[t][q] = 0.f;

        {
            const uint32_t abase = sbase + cur * AB;
            #pragma unroll
            for (int k0 = 0; k0 < H; k0 += 16) {
                uint32_t a[4];
                const uint32_t a_off = ((wrow + a_row_off) * SA + k0 + (lm >> 1) * 8) * 2;
                ldm_x4(a, abase + a_off);
                #pragma unroll
                for (int np = 0; np < NT8W / 2; np++) {
                    uint32_t b[4];
                    const uint32_t b_off = ((wcol + np * 16 + b_row_off) * SA + k0 + (lm & 1) * 8) * 2;
                    ldm_x4(b, sbase + OFF_B + b_off);
                    mma_f16(c[2 * np],     a, &b[0]);
                    mma_f16(c[2 * np + 1], a, &b[2]);
                }
            }
        }
        const int nt = tile + gridDim.x;
        if (nt < NT) build(nt, cur ^ 1);
        if constexpr (!FINAL) { if (prev >= 0) ymma(prev); }
        __syncthreads();

        // ---- store C frags to z (= A(cur) region, fp16, row stride SA) ----
        __half* z = (__half*)(smem + cur * AB);
        {
            const int qr = lid >> 2, qc = (lid & 3) * 2;
            #pragma unroll
            for (int t = 0; t < NT8W; t++) {
                const int col = wcol + t * 8 + qc;
                *(uint32_t*)&z[(wrow + qr) * SA + col]     = pack_h2(c[t][0], c[t][1]);
                *(uint32_t*)&z[(wrow + qr + 8) * SA + col] = pack_h2(c[t][2], c[t][3]);
            }
        }
        __syncthreads();

        // ---- 6-row max + bias + relu -> hY (or out) ----
        for (int t = tid; t < NODES * (N / 2); t += TH) {
            const int g = t / (N / 2), c2 = (t % (N / 2)) * 2;
            const int node = tile * NODES + g;
            const __half2* zp = (const __half2*)(z + (6 * g) * SA + c2);
            constexpr int S2 = SA / 2;
            __half2 m = zp[0];
            m = __hmax2(m, zp[S2]);
            m = __hmax2(m, zp[2 * S2]);
            m = __hmax2(m, zp[3 * S2]);
            m = __hmax2(m, zp[4 * S2]);
            m = __hmax2(m, zp[5 * S2]);
            const float2 bf = *(const float2*)&sbb[c2];
            const float r0 = fmaxf(__low2float(m)  + bf.x, 0.f);
            const float r1 = fmaxf(__high2float(m) + bf.y, 0.f);
            if constexpr (FINAL) {
                if (node < NNODES)
                    *(float2*)&outF[(size_t)node * N + c2] = make_float2(r0, r1);
            } else {
                hY[g * SAY + c2]     = __float2half_rn(r0);
                hY[g * SAY + c2 + 1] = __float2half_rn(r1);
            }
        }
        prev = tile;
        cur ^= 1;
    }

    if constexpr (!FINAL) {
        if (prev >= 0) {
            __syncthreads();   // final epilogue's hY writes visible
            ymma(prev);
        }
    }
}

template<int H, int N, int H2, int TH, int WX, bool FINAL>
static constexpr int smemF() {
    constexpr int M   = 16 * (TH / 32 / WX);
    constexpr int SA  = H + 8;
    constexpr int SAY = N + 8;
    int s = 2 * M * SA * 2 + N * SA * 2 + 3 * H * 4 + N * 4;
    if (!FINAL) s += H2 * SAY * 2 + H2 * 4 + 48 * SAY * 2;
    return s + 64;
}

// ---------------- host ----------------
extern "C" void kernel_launch(void* const* d_in, const int* in_sizes, int n_in,
                              void* d_out, int out_size)
{
    const float* pos = (const float*)d_in[0];
    const int*   src = (const int*)d_in[1];   // row 0 of edge_index
    const float* W1a = (const float*)d_in[2];
    const float* b1a = (const float*)d_in[3];
    const float* W1b = (const float*)d_in[4];
    const float* b1b = (const float*)d_in[5];
    const float* W2a = (const float*)d_in[6];
    const float* b2a = (const float*)d_in[7];
    const float* W2b = (const float*)d_in[8];
    const float* b2b = (const float*)d_in[9];
    const float* W3a = (const float*)d_in[10];
    const float* b3a = (const float*)d_in[11];
    const float* W3b = (const float*)d_in[12];
    const float* b3b = (const float*)d_in[13];
    float* out = (float*)d_out;

    __half *ya, *yb;
    float4* ed;
    cudaGetSymbolAddress((void**)&ya, g_ya);
    cudaGetSymbolAddress((void**)&yb, g_yb);
    cudaGetSymbolAddress((void**)&ed, g_ed);

    constexpr int S1 = smemF<32, 32, 64, 512, 1, false>();     // ~53 KB  (2 CTAs/SM)
    constexpr int S2 = smemF<64, 64, 128, 512, 1, false>();    // ~110 KB (2 CTAs/SM)
    constexpr int S3 = smemF<128, 128, 16, 512, 2, true>();    // ~107 KB (2 CTAs/SM)
    cudaFuncSetAttribute(stage2F<32, 32, 64, 512, 1, 2, false>,   cudaFuncAttributeMaxDynamicSharedMemorySize, S1);
    cudaFuncSetAttribute(stage2F<64, 64, 128, 512, 1, 2, false>,  cudaFuncAttributeMaxDynamicSharedMemorySize, S2);
    cudaFuncSetAttribute(stage2F<128, 128, 16, 512, 2, 2, true>,  cudaFuncAttributeMaxDynamicSharedMemorySize, S3);

    // prep: edge table + layer-1 node GEMM (y1 -> ya)
    prepE<<<1024, 256>>>(pos, src, ed, W1a, b1a, ya);

    // layer 1: edge GEMM (32) + max + fused node GEMM for layer 2 (y2 -> yb)
    stage2F<32, 32, 64, 512, 1, 2, false><<<296, 512, S1>>>(ya, ed, W1a, 3, W1b, b1b, W2a, b2a, yb, nullptr);

    // layer 2: edge GEMM (64) + max + fused node GEMM for layer 3 (y3 -> ya)
    stage2F<64, 64, 128, 512, 1, 2, false><<<296, 512, S2>>>(yb, ed, W2a, 32, W2b, b2b, W3a, b3a, ya, nullptr);

    // layer 3: edge GEMM (128) + max -> final out (fp32), col-split warps
    stage2F<128, 128, 16, 512, 2, 2, true><<<296, 512, S3>>>(ya, ed, W3a, 64, W3b, b3b, nullptr, nullptr, nullptr, out);
}

// round 13
// speedup vs baseline: 2.9916x; 1.0153x over previous
#include <cuda_runtime.h>
#include <cuda_fp16.h>
#include <stdint.h>

#define NNODES 100000
#define KNN 6
#define NEDGES 600000

// ---------------- device scratch (no allocation allowed) ----------------
__device__ __half g_ya[(size_t)NNODES * 128];  // y ping
__device__ __half g_yb[(size_t)NNODES * 128];  // y pong
__device__ float4 g_ed[NEDGES];                // per-edge: (bitcast j, d0, d1, d2)

// ---------------- PTX helpers (sm_80+: mma.sync / ldmatrix) ----------------
__device__ __forceinline__ uint32_t s2u(const void* p) {
    uint32_t a;
    asm("{ .reg .u64 t; cvta.to.shared.u64 t, %1; cvt.u32.u64 %0, t; }" : "=r"(a) : "l"(p));
    return a;
}
__device__ __forceinline__ void ldm_x4(uint32_t* r, uint32_t addr) {
    asm volatile("ldmatrix.sync.aligned.m8n8.x4.shared.b16 {%0,%1,%2,%3}, [%4];"
                 : "=r"(r[0]), "=r"(r[1]), "=r"(r[2]), "=r"(r[3]) : "r"(addr));
}
__device__ __forceinline__ void mma_f16(float* c, const uint32_t* a, const uint32_t* b) {
    asm volatile("mma.sync.aligned.m16n8k16.row.col.f32.f16.f16.f32 "
                 "{%0,%1,%2,%3}, {%4,%5,%6,%7}, {%8,%9}, {%0,%1,%2,%3};"
                 : "+f"(c[0]), "+f"(c[1]), "+f"(c[2]), "+f"(c[3])
                 : "r"(a[0]), "r"(a[1]), "r"(a[2]), "r"(a[3]), "r"(b[0]), "r"(b[1]));
}
__device__ __forceinline__ uint32_t pack_h2(float a, float b) {
    __half2 v = __floats2half2_rn(a, b);
    return *(uint32_t*)&v;
}

// ============ prepE: per-edge (j, dpos) + layer-1 node GEMM (fused) ============
__global__ __launch_bounds__(256) void prepE(const float* __restrict__ pos,
                                             const int*   __restrict__ src,
                                             float4* __restrict__ ed,
                                             const float* __restrict__ W1a,
                                             const float* __restrict__ b1a,
                                             __half* __restrict__ y1)
{
    __shared__ float sW[3 * 32];
    __shared__ float sb[32];
    for (int t = threadIdx.x; t < 3 * 32; t += 256) sW[t] = W1a[t];
    for (int t = threadIdx.x; t < 32;     t += 256) sb[t] = b1a[t];
    __syncthreads();

    for (int e = blockIdx.x * 256 + threadIdx.x; e < NEDGES; e += gridDim.x * 256) {
        const int i = e / KNN;
        const int j = __ldg(&src[e]);
        float4 v;
        v.x = __int_as_float(j);
        v.y = __ldg(&pos[3 * j + 0]) - __ldg(&pos[3 * i + 0]);
        v.z = __ldg(&pos[3 * j + 1]) - __ldg(&pos[3 * i + 1]);
        v.w = __ldg(&pos[3 * j + 2]) - __ldg(&pos[3 * i + 2]);
        ed[e] = v;
    }

    const int lane = threadIdx.x & 31;
    const int gw = (blockIdx.x * 256 + threadIdx.x) >> 5;
    const int nw = (gridDim.x * 256) >> 5;
    for (int node = gw; node < NNODES; node += nw) {
        const float x0 = __ldg(&pos[3 * node]), x1 = __ldg(&pos[3 * node + 1]), x2 = __ldg(&pos[3 * node + 2]);
        float acc = sb[lane];
        acc = fmaf(x0, sW[lane], acc);
        acc = fmaf(x1, sW[32 + lane], acc);
        acc = fmaf(x2, sW[64 + lane], acc);
        y1[(size_t)node * 32 + lane] = __float2half_rn(acc);
    }
}

// ============ stage2F: pipelined fused edge-GEMM + 6-row max + fused next-layer node GEMM ===
// Warp grid: WY=NWARP/WX row-warps x WX col-warps; M = 16*WY rows, NC = N/WX cols/warp
// (16 accums/thread at all configs). Separate z buffer: z-store happens inside the
// parallel section (depends only on own MMA results) -> 2 syncs per tile.
// Section = { edge-MMA(t), build(t+1), z-store(t), yMMA(t-1) }.
template<int H, int N, int H2, int TH, int WX, int MINB, bool FINAL>
__global__ __launch_bounds__(TH, MINB) void stage2F(const __half* __restrict__ y,
                                                    const float4* __restrict__ ed,
                                                    const float* __restrict__ Wa,   // [(cin+3)][H]
                                                    int cin,
                                                    const float* __restrict__ Wb,   // [H][N]
                                                    const float* __restrict__ bb,
                                                    const float* __restrict__ WaN,  // [N][H2] (top rows)
                                                    const float* __restrict__ baN,
                                                    __half* __restrict__ yN,
                                                    float* __restrict__ outF)
{
    constexpr int NWARP = TH / 32;
    constexpr int WY    = NWARP / WX;
    constexpr int M     = 16 * WY;
    constexpr int EP    = (M / KNN) * KNN;
    constexpr int NODES = M / KNN;
    constexpr int SA    = H + 8;            // A/B row stride (halfs)
    constexpr int SZ    = N + 8;            // z row stride (halfs)
    constexpr int SAY   = N + 8;            // hY/B2 row stride (halfs)
    constexpr int NC    = N / WX;           // cols per warp
    constexpr int NT8W  = NC / 8;
    constexpr int G4    = H / 4;
    constexpr int RS4   = TH / G4;
    constexpr int AB    = M * SA * 2;
    constexpr int OFF_B  = 2 * AB;
    constexpr int OFF_Z  = OFF_B + N * SA * 2;
    constexpr int OFF_WP = OFF_Z + M * SZ * 2;
    constexpr int OFF_BB = OFF_WP + 3 * H * 4;
    constexpr int OFF_B2 = OFF_BB + N * 4;
    constexpr int OFF_BA2= OFF_B2 + (FINAL ? 0 : H2 * SAY * 2);
    constexpr int OFF_HY = OFF_BA2 + (FINAL ? 0 : H2 * 4);

    extern __shared__ char smem[];
    const uint32_t sbase = s2u(smem);
    __half* z  = (__half*)(smem + OFF_Z);
    float* sWp = (float*)(smem + OFF_WP);
    float* sbb = (float*)(smem + OFF_BB);
    float* sba2= (float*)(smem + OFF_BA2);
    __half* hY = (__half*)(smem + OFF_HY);

    const int tid  = threadIdx.x;
    const int wid  = tid >> 5;
    const int lid  = tid & 31;
    const int wy   = wid % WY;
    const int wx   = wid / WY;
    const int wrow = wy * 16;
    const int wcol = wx * NC;

    // ---- block prologue ----
    const float* Wp = Wa + (size_t)cin * H;
    for (int t = tid; t < 3 * H; t += TH) sWp[t] = Wp[t];
    for (int t = tid; t < N;     t += TH) sbb[t] = bb[t];
    for (int t = tid; t < N * H; t += TH) {
        int n = t / H, k = t % H;
        *(__half*)(smem + OFF_B + (n * SA + k) * 2) = __float2half_rn(Wb[(size_t)k * N + n]);
    }
    if constexpr (!FINAL) {
        for (int t = tid; t < H2 * N; t += TH) {
            int n2 = t / N, k = t % N;
            *(__half*)(smem + OFF_B2 + (n2 * SAY + k) * 2) = __float2half_rn(WaN[(size_t)k * H2 + n2]);
        }
        for (int t = tid; t < H2; t += TH) sba2[t] = baN[t];
    }
    __syncthreads();

    // ---- hoist Wa_pos (4 fixed channels per thread) ----
    const int g4 = tid % G4;
    const int rt = tid / G4;
    const int cb = 4 * g4;
    float w[3][4];
    #pragma unroll
    for (int d = 0; d < 3; d++)
        #pragma unroll
        for (int q = 0; q < 4; q++) w[d][q] = sWp[d * H + cb + q];

    const int lm = lid >> 3, lr = lid & 7;
    const int a_row_off = (lm & 1) * 8 + lr;
    const int b_row_off = (lm >> 1) * 8 + lr;
    const int NT = (NEDGES + EP - 1) / EP;

    auto build = [&](int t, int buf) {
        const int ebase = t * EP;
        char* A = smem + buf * AB;
        #pragma unroll 4
        for (int r = rt; r < M; r += RS4) {
            const int ge = ebase + r;
            uint2 hv = make_uint2(0u, 0u);
            if (r < EP && ge < NEDGES) {
                const float4 e4 = __ldg(&ed[ge]);
                const int j = __float_as_int(e4.x);
                const uint2 yr = *(const uint2*)&y[(size_t)j * H + cb];
                const __half2 y01 = *(const __half2*)&yr.x;
                const __half2 y23 = *(const __half2*)&yr.y;
                float v0 = __low2float(y01),  v1 = __high2float(y01);
                float v2 = __low2float(y23),  v3 = __high2float(y23);
                v0 = fmaf(e4.y, w[0][0], fmaf(e4.z, w[1][0], fmaf(e4.w, w[2][0], v0)));
                v1 = fmaf(e4.y, w[0][1], fmaf(e4.z, w[1][1], fmaf(e4.w, w[2][1], v1)));
                v2 = fmaf(e4.y, w[0][2], fmaf(e4.z, w[1][2], fmaf(e4.w, w[2][2], v2)));
                v3 = fmaf(e4.y, w[0][3], fmaf(e4.z, w[1][3], fmaf(e4.w, w[2][3], v3)));
                hv.x = pack_h2(fmaxf(v0, 0.f), fmaxf(v1, 0.f));
                hv.y = pack_h2(fmaxf(v2, 0.f), fmaxf(v3, 0.f));
            }
            *(uint2*)(A + (r * SA + cb) * 2) = hv;
        }
    };

    // ---- yMMA: y_next[tile nodes] = hY @ WaNext^T + baNext ----
    auto ymma = [&](int ptile) {
        const int pbase = ptile * NODES;
        constexpr int MT = (NODES + 15) / 16;
        for (int task = wid; task < MT * (H2 / 16); task += NWARP) {
            const int mt = task % MT;
            const int nb = (task / MT) * 16;
            float cc[2][4] = {{0.f,0.f,0.f,0.f},{0.f,0.f,0.f,0.f}};
            #pragma unroll
            for (int k0 = 0; k0 < N; k0 += 16) {
                uint32_t a[4], b[4];
                ldm_x4(a, sbase + OFF_HY + ((mt * 16 + a_row_off) * SAY + k0 + (lm >> 1) * 8) * 2);
                ldm_x4(b, sbase + OFF_B2 + ((nb + b_row_off) * SAY + k0 + (lm & 1) * 8) * 2);
                mma_f16(cc[0], a, &b[0]);
                mma_f16(cc[1], a, &b[2]);
            }
            const int qr = lid >> 2, qc = (lid & 3) * 2;
            #pragma unroll
            for (int hh = 0; hh < 2; hh++) {
                const int col = nb + hh * 8 + qc;
                const float2 bf = *(const float2*)&sba2[col];
                const int r0 = mt * 16 + qr, r1 = r0 + 8;
                if (r0 < NODES) {
                    const int n0 = pbase + r0;
                    if (n0 < NNODES)
                        *(uint32_t*)&yN[(size_t)n0 * H2 + col] = pack_h2(cc[hh][0] + bf.x, cc[hh][1] + bf.y);
                }
                if (r1 < NODES) {
                    const int n1 = pbase + r1;
                    if (n1 < NNODES)
                        *(uint32_t*)&yN[(size_t)n1 * H2 + col] = pack_h2(cc[hh][2] + bf.x, cc[hh][3] + bf.y);
                }
            }
        }
    };

    int cur = 0;
    int prev = -1;
    if (blockIdx.x < NT) build(blockIdx.x, 0);

    for (int tile = blockIdx.x; tile < NT; tile += gridDim.x) {
        __syncthreads();   // A(cur) built; prev epilogue done (z, hY consumed)

        // ---- parallel section: edge-MMA(cur) + build(next) + z-store + yMMA(prev) ----
        float c[NT8W][4];
        #pragma unroll
        for (int t = 0; t < NT8W; t++)
            #pragma unroll
            for (int q = 0; q < 4; q++) c[t][q] = 0.f;

        {
            const uint32_t abase = sbase + cur * AB;
            #pragma unroll
            for (int k0 = 0; k0 < H; k0 += 16) {
                uint32_t a[4];
                const uint32_t a_off = ((wrow + a_row_off) * SA + k0 + (lm >> 1) * 8) * 2;
                ldm_x4(a, abase + a_off);
                #pragma unroll
                for (int np = 0; np < NT8W / 2; np++) {
                    uint32_t b[4];
                    const uint32_t b_off = ((wcol + np * 16 + b_row_off) * SA + k0 + (lm & 1) * 8) * 2;
                    ldm_x4(b, sbase + OFF_B + b_off);
                    mma_f16(c[2 * np],     a, &b[0]);
                    mma_f16(c[2 * np + 1], a, &b[2]);
                }
            }
        }
        const int nt = tile + gridDim.x;
        if (nt < NT) build(nt, cur ^ 1);

        // z-store: own fragments only, no inter-warp dependency
        {
            const int qr = lid >> 2, qc = (lid & 3) * 2;
            #pragma unroll
            for (int t = 0; t < NT8W; t++) {
                const int col = wcol + t * 8 + qc;
                *(uint32_t*)&z[(wrow + qr) * SZ + col]     = pack_h2(c[t][0], c[t][1]);
                *(uint32_t*)&z[(wrow + qr + 8) * SZ + col] = pack_h2(c[t][2], c[t][3]);
            }
        }
        if constexpr (!FINAL) { if (prev >= 0) ymma(prev); }
        __syncthreads();   // z complete; A(next) built

        // ---- 6-row max + bias + relu -> hY (or out) ----
        for (int t = tid; t < NODES * (N / 2); t += TH) {
            const int g = t / (N / 2), c2 = (t % (N / 2)) * 2;
            const int node = tile * NODES + g;
            const __half2* zp = (const __half2*)(z + (6 * g) * SZ + c2);
            constexpr int S2 = SZ / 2;
            __half2 m = zp[0];
            m = __hmax2(m, zp[S2]);
            m = __hmax2(m, zp[2 * S2]);
            m = __hmax2(m, zp[3 * S2]);
            m = __hmax2(m, zp[4 * S2]);
            m = __hmax2(m, zp[5 * S2]);
            const float2 bf = *(const float2*)&sbb[c2];
            const float r0 = fmaxf(__low2float(m)  + bf.x, 0.f);
            const float r1 = fmaxf(__high2float(m) + bf.y, 0.f);
            if constexpr (FINAL) {
                if (node < NNODES)
                    *(float2*)&outF[(size_t)node * N + c2] = make_float2(r0, r1);
            } else {
                hY[g * SAY + c2]     = __float2half_rn(r0);
                hY[g * SAY + c2 + 1] = __float2half_rn(r1);
            }
        }
        prev = tile;
        cur ^= 1;
    }

    if constexpr (!FINAL) {
        if (prev >= 0) {
            __syncthreads();   // final epilogue's hY writes visible
            ymma(prev);
        }
    }
}

template<int H, int N, int H2, int TH, int WX, bool FINAL>
static constexpr int smemF() {
    constexpr int M   = 16 * (TH / 32 / WX);
    constexpr int SA  = H + 8;
    constexpr int SZ  = N + 8;
    constexpr int SAY = N + 8;
    int s = 2 * M * SA * 2 + N * SA * 2 + M * SZ * 2 + 3 * H * 4 + N * 4;
    if (!FINAL) s += H2 * SAY * 2 + H2 * 4 + 48 * SAY * 2;
    return s + 64;
}

// ---------------- host ----------------
extern "C" void kernel_launch(void* const* d_in, const int* in_sizes, int n_in,
                              void* d_out, int out_size)
{
    const float* pos = (const float*)d_in[0];
    const int*   src = (const int*)d_in[1];   // row 0 of edge_index
    const float* W1a = (const float*)d_in[2];
    const float* b1a = (const float*)d_in[3];
    const float* W1b = (const float*)d_in[4];
    const float* b1b = (const float*)d_in[5];
    const float* W2a = (const float*)d_in[6];
    const float* b2a = (const float*)d_in[7];
    const float* W2b = (const float*)d_in[8];
    const float* b2b = (const float*)d_in[9];
    const float* W3a = (const float*)d_in[10];
    const float* b3a = (const float*)d_in[11];
    const float* W3b = (const float*)d_in[12];
    const float* b3b = (const float*)d_in[13];
    float* out = (float*)d_out;

    __half *ya, *yb;
    float4* ed;
    cudaGetSymbolAddress((void**)&ya, g_ya);
    cudaGetSymbolAddress((void**)&yb, g_yb);
    cudaGetSymbolAddress((void**)&ed, g_ed);

    constexpr int S1 = smemF<32, 32, 64, 512, 1, false>();     // ~74 KB  (2 CTAs/SM)
    constexpr int S2 = smemF<64, 64, 128, 512, 2, false>();    // ~101 KB (2 CTAs/SM)
    constexpr int S3 = smemF<128, 128, 16, 512, 4, true>();    // ~89 KB  (2 CTAs/SM)
    cudaFuncSetAttribute(stage2F<32, 32, 64, 512, 1, 2, false>,   cudaFuncAttributeMaxDynamicSharedMemorySize, S1);
    cudaFuncSetAttribute(stage2F<64, 64, 128, 512, 2, 2, false>,  cudaFuncAttributeMaxDynamicSharedMemorySize, S2);
    cudaFuncSetAttribute(stage2F<128, 128, 16, 512, 4, 2, true>,  cudaFuncAttributeMaxDynamicSharedMemorySize, S3);

    // prep: edge table + layer-1 node GEMM (y1 -> ya)
    prepE<<<1024, 256>>>(pos, src, ed, W1a, b1a, ya);

    // layer 1: edge GEMM (32) + max + fused node GEMM for layer 2 (y2 -> yb)
    stage2F<32, 32, 64, 512, 1, 2, false><<<296, 512, S1>>>(ya, ed, W1a, 3, W1b, b1b, W2a, b2a, yb, nullptr);

    // layer 2: edge GEMM (64) + max + fused node GEMM for layer 3 (y3 -> ya)
    stage2F<64, 64, 128, 512, 2, 2, false><<<296, 512, S2>>>(yb, ed, W2a, 32, W2b, b2b, W3a, b3a, ya, nullptr);

    // layer 3: edge GEMM (128) + max -> final out (fp32), 4-way col-split warps
    stage2F<128, 128, 16, 512, 4, 2, true><<<296, 512, S3>>>(ya, ed, W3a, 64, W3b, b3b, nullptr, nullptr, nullptr, out);
}